// round 1
// baseline (speedup 1.0000x reference)
#include <cuda_runtime.h>

#define NN 100000
#define EE 1600000
#define FIN 32
#define HD 128

// ---------------- persistent device scratch (no allocs allowed) ----------------
__device__ float g_bufA[(size_t)NN * HD];
__device__ float g_bufB[(size_t)NN * HD];
__device__ float g_agg [(size_t)NN * HD];
__device__ float g_tmp [(size_t)NN * HD];
__device__ int   g_deg[NN];
__device__ int   g_rowptr[NN + 1];
__device__ int   g_pos[NN];
__device__ int   g_col[EE];
__device__ int   g_is64;

// ---------------- edge-index dtype detection (int64 vs int32) ----------------
// jax.random.randint(dtype=int64) silently yields int32 when x64 is disabled.
// If the buffer is int64 (values in [0,N) >= 0), every odd int32 word is 0.
__global__ void k_detect(const void* ei) {
    __shared__ int s_nz;
    if (threadIdx.x == 0) s_nz = 0;
    __syncthreads();
    const int* p = (const int*)ei;
    for (int i = threadIdx.x; i < 8192; i += blockDim.x) {
        if (p[2 * i + 1] != 0) s_nz = 1;   // benign race; any write -> 1
    }
    __syncthreads();
    if (threadIdx.x == 0) g_is64 = (s_nz == 0) ? 1 : 0;
}

__device__ __forceinline__ int edge_at(const void* ei, long long idx) {
    if (g_is64) return (int)((const long long*)ei)[idx];
    return ((const int*)ei)[idx];
}

// ---------------- CSR build ----------------
__global__ void k_zero_deg() {
    int i = blockIdx.x * blockDim.x + threadIdx.x;
    if (i < NN) g_deg[i] = 0;
}

__global__ void k_count(const void* ei) {
    int e = blockIdx.x * blockDim.x + threadIdx.x;
    if (e >= EE) return;
    atomicAdd(&g_deg[edge_at(ei, (long long)EE + e)], 1);
}

__global__ void k_scan() {
    __shared__ int part[1024];
    int tid = threadIdx.x;
    const int chunk = (NN + 1023) / 1024;
    int start = tid * chunk;
    int end = start + chunk; if (end > NN) end = NN;
    int s = 0;
    for (int i = start; i < end; i++) s += g_deg[i];
    part[tid] = s;
    __syncthreads();
    if (tid == 0) {
        int run = 0;
        for (int i = 0; i < 1024; i++) { int v = part[i]; part[i] = run; run += v; }
        g_rowptr[NN] = run;
    }
    __syncthreads();
    int run = part[tid];
    for (int i = start; i < end; i++) {
        g_rowptr[i] = run;
        g_pos[i]    = run;
        run += g_deg[i];
    }
}

__global__ void k_fill(const void* ei) {
    int e = blockIdx.x * blockDim.x + threadIdx.x;
    if (e >= EE) return;
    int s = edge_at(ei, e);
    int d = edge_at(ei, (long long)EE + e);
    int p = atomicAdd(&g_pos[d], 1);
    g_col[p] = s;
}

// ---------------- mean aggregation: warp per node, CSR gather ----------------
template <int DIM>
__global__ void k_aggregate(const float* __restrict__ hin, float* __restrict__ agg) {
    int w = (blockIdx.x * blockDim.x + threadIdx.x) >> 5;
    int lane = threadIdx.x & 31;
    if (w >= NN) return;
    int beg = g_rowptr[w], end = g_rowptr[w + 1];
    float inv = 1.f / fmaxf((float)(end - beg), 1.f);
    if (DIM == 128) {
        float ax = 0.f, ay = 0.f, az = 0.f, aw = 0.f;
        for (int e = beg; e < end; e++) {
            int s = g_col[e];
            float4 v = *(const float4*)(hin + (size_t)s * 128 + lane * 4);
            ax += v.x; ay += v.y; az += v.z; aw += v.w;
        }
        float4 o; o.x = ax * inv; o.y = ay * inv; o.z = az * inv; o.w = aw * inv;
        *(float4*)(agg + (size_t)w * 128 + lane * 4) = o;
    } else {
        float a = 0.f;
        for (int e = beg; e < end; e++)
            a += hin[(size_t)g_col[e] * DIM + lane];
        agg[(size_t)w * DIM + lane] = a * inv;
    }
}

// ---------------- GEMM: out[N,128] = [A1|A2][N,Ktot] @ [W1;W2][Ktot,128] + bias
// block tile 64 nodes x 128 cols, 256 threads, 4x8 register blocking.
__global__ __launch_bounds__(256) void k_gemm(
    const float* __restrict__ A1, const float* __restrict__ A2,
    const float* __restrict__ W1, const float* __restrict__ W2,
    const float* __restrict__ bias, float* __restrict__ out,
    int kin, int Ktot)
{
    __shared__ float At[16][64];    // transposed A chunk: [k][node]
    __shared__ float Wt[16][128];   // W chunk: [k][col]

    int tid   = threadIdx.x;
    int node0 = blockIdx.x * 64;
    int tx = tid & 15;              // col group: cols tx*8 .. tx*8+7
    int ty = tid >> 4;              // row group: nodes ty*4 .. ty*4+3

    float acc[4][8];
#pragma unroll
    for (int i = 0; i < 4; i++)
#pragma unroll
        for (int j = 0; j < 8; j++) acc[i][j] = 0.f;

    int an  = tid & 63;             // node within tile for A-load
    int akq = tid >> 6;             // which float4 of the 16-k chunk
    int wr  = tid >> 5;             // W row within chunk (and +8)
    int wc  = (tid & 31) * 4;       // W col (float4)

    for (int k0 = 0; k0 < Ktot; k0 += 16) {
        // --- stage A (transposed) ---
        {
            int kg = k0 + akq * 4;
            const float* Asrc; int kk;
            if (kg < kin) { Asrc = A1; kk = kg; } else { Asrc = A2; kk = kg - kin; }
            int node = node0 + an;
            float4 v = make_float4(0.f, 0.f, 0.f, 0.f);
            if (node < NN) v = *(const float4*)(Asrc + (size_t)node * kin + kk);
            At[akq * 4 + 0][an] = v.x;
            At[akq * 4 + 1][an] = v.y;
            At[akq * 4 + 2][an] = v.z;
            At[akq * 4 + 3][an] = v.w;
        }
        // --- stage W ---
#pragma unroll
        for (int rr = 0; rr < 2; rr++) {
            int r = wr + rr * 8;
            int kg2 = k0 + r;
            const float* Wsrc = (kg2 < kin) ? (W1 + (size_t)kg2 * HD)
                                            : (W2 + (size_t)(kg2 - kin) * HD);
            *(float4*)&Wt[r][wc] = *(const float4*)(Wsrc + wc);
        }
        __syncthreads();
        // --- compute ---
#pragma unroll
        for (int kk = 0; kk < 16; kk++) {
            float4 a4 = *(const float4*)&At[kk][ty * 4];
            float4 w0 = *(const float4*)&Wt[kk][tx * 8];
            float4 w1 = *(const float4*)&Wt[kk][tx * 8 + 4];
            float av[4] = {a4.x, a4.y, a4.z, a4.w};
            float wv[8] = {w0.x, w0.y, w0.z, w0.w, w1.x, w1.y, w1.z, w1.w};
#pragma unroll
            for (int i = 0; i < 4; i++)
#pragma unroll
                for (int j = 0; j < 8; j++)
                    acc[i][j] += av[i] * wv[j];
        }
        __syncthreads();
    }

#pragma unroll
    for (int i = 0; i < 4; i++) {
        int node = node0 + ty * 4 + i;
        if (node >= NN) continue;
#pragma unroll
        for (int j = 0; j < 8; j += 4) {
            int c = tx * 8 + j;
            float4 o;
            o.x = acc[i][j + 0] + (bias ? bias[c + 0] : 0.f);
            o.y = acc[i][j + 1] + (bias ? bias[c + 1] : 0.f);
            o.z = acc[i][j + 2] + (bias ? bias[c + 2] : 0.f);
            o.w = acc[i][j + 3] + (bias ? bias[c + 3] : 0.f);
            *(float4*)(out + (size_t)node * HD + c) = o;
        }
    }
}

// ---------------- LayerNorm + relu + residual: warp per node ----------------
__global__ void k_ln(const float* __restrict__ t, const float* __restrict__ res,
                     const float* __restrict__ gamma, const float* __restrict__ beta,
                     float* __restrict__ out)
{
    int w = (blockIdx.x * blockDim.x + threadIdx.x) >> 5;
    int lane = threadIdx.x & 31;
    if (w >= NN) return;
    float4 v = *(const float4*)(t + (size_t)w * 128 + lane * 4);
    float s = v.x + v.y + v.z + v.w;
#pragma unroll
    for (int o = 16; o; o >>= 1) s += __shfl_xor_sync(0xFFFFFFFFu, s, o);
    float mu = s * (1.f / 128.f);
    float dx = v.x - mu, dy = v.y - mu, dz = v.z - mu, dw = v.w - mu;
    float q = dx * dx + dy * dy + dz * dz + dw * dw;
#pragma unroll
    for (int o = 16; o; o >>= 1) q += __shfl_xor_sync(0xFFFFFFFFu, q, o);
    float rstd = rsqrtf(q * (1.f / 128.f) + 1e-5f);
    float4 g4 = *(const float4*)(gamma + lane * 4);
    float4 b4 = *(const float4*)(beta  + lane * 4);
    float4 r4 = *(const float4*)(res + (size_t)w * 128 + lane * 4);
    float4 o4;
    o4.x = fmaxf(dx * rstd * g4.x + b4.x, 0.f) + r4.x;
    o4.y = fmaxf(dy * rstd * g4.y + b4.y, 0.f) + r4.y;
    o4.z = fmaxf(dz * rstd * g4.z + b4.z, 0.f) + r4.z;
    o4.w = fmaxf(dw * rstd * g4.w + b4.w, 0.f) + r4.w;
    *(float4*)(out + (size_t)w * 128 + lane * 4) = o4;
}

// ---------------- head: yhat = h @ Wh + bh, warp per node ----------------
__global__ void k_head(const float* __restrict__ h, const float* __restrict__ Wh,
                       const float* __restrict__ bh, float* __restrict__ y)
{
    int w = (blockIdx.x * blockDim.x + threadIdx.x) >> 5;
    int lane = threadIdx.x & 31;
    if (w >= NN) return;
    float4 v  = *(const float4*)(h  + (size_t)w * 128 + lane * 4);
    float4 wv = *(const float4*)(Wh + lane * 4);
    float s = v.x * wv.x + v.y * wv.y + v.z * wv.z + v.w * wv.w;
#pragma unroll
    for (int o = 16; o; o >>= 1) s += __shfl_xor_sync(0xFFFFFFFFu, s, o);
    if (lane == 0) y[w] = s + bh[0];
}

// ---------------- launcher ----------------
extern "C" void kernel_launch(void* const* d_in, const int* in_sizes, int n_in,
                              void* d_out, int out_size)
{
    const float* x     = (const float*)d_in[0];
    const void*  ei    = d_in[1];
    const float* Wl0   = (const float*)d_in[2];
    const float* bl0   = (const float*)d_in[3];
    const float* Wr0   = (const float*)d_in[4];
    const float* g0    = (const float*)d_in[5];
    const float* be0   = (const float*)d_in[6];
    const float* Wl1   = (const float*)d_in[7];
    const float* bl1   = (const float*)d_in[8];
    const float* Wr1   = (const float*)d_in[9];
    const float* g1    = (const float*)d_in[10];
    const float* be1   = (const float*)d_in[11];
    const float* Wl2   = (const float*)d_in[12];
    const float* bl2   = (const float*)d_in[13];
    const float* Wr2   = (const float*)d_in[14];
    const float* g2    = (const float*)d_in[15];
    const float* be2   = (const float*)d_in[16];
    const float* Wproj = (const float*)d_in[17];
    const float* Wh    = (const float*)d_in[18];
    const float* bh    = (const float*)d_in[19];

    float* out = (float*)d_out;

    // device pointers for the scratch globals
    float *pA, *pB, *pAgg, *pTmp;
    cudaGetSymbolAddress((void**)&pA,   g_bufA);
    cudaGetSymbolAddress((void**)&pB,   g_bufB);
    cudaGetSymbolAddress((void**)&pAgg, g_agg);
    cudaGetSymbolAddress((void**)&pTmp, g_tmp);

    // final h target: directly into d_out if it holds [yhat, h]
    float* hout = (out_size >= NN + NN * HD) ? (out + NN) : pA;

    const int TB = 256;
    dim3 gN((NN + TB - 1) / TB), gE((EE + TB - 1) / TB);
    dim3 gWarp((NN + 7) / 8);               // 8 warps / 256-thread block
    dim3 gGemm((NN + 63) / 64);

    // CSR build (per call; edges fixed but no caching allowed)
    k_detect<<<1, 256>>>(ei);
    k_zero_deg<<<gN, TB>>>();
    k_count<<<gE, TB>>>(ei);
    k_scan<<<1, 1024>>>();
    k_fill<<<gE, TB>>>(ei);

    // ---- layer 0 ----
    k_aggregate<FIN><<<gWarp, TB>>>(x, pAgg);
    k_gemm<<<gGemm, TB>>>(pAgg, x, Wl0, Wr0, bl0, pTmp, FIN, 2 * FIN);
    k_gemm<<<gGemm, TB>>>(x, x, Wproj, Wproj, nullptr, pB, FIN, FIN); // proj = x @ Wproj
    k_ln<<<gWarp, TB>>>(pTmp, pB, g0, be0, pA);

    // ---- layer 1 ----
    k_aggregate<HD><<<gWarp, TB>>>(pA, pAgg);
    k_gemm<<<gGemm, TB>>>(pAgg, pA, Wl1, Wr1, bl1, pTmp, HD, 2 * HD);
    k_ln<<<gWarp, TB>>>(pTmp, pA, g1, be1, pB);

    // ---- layer 2 ----
    k_aggregate<HD><<<gWarp, TB>>>(pB, pAgg);
    k_gemm<<<gGemm, TB>>>(pAgg, pB, Wl2, Wr2, bl2, pTmp, HD, 2 * HD);
    k_ln<<<gWarp, TB>>>(pTmp, pB, g2, be2, hout);

    // ---- head ----
    k_head<<<gWarp, TB>>>(hout, Wh, bh, out);
}

// round 2
// speedup vs baseline: 1.8172x; 1.8172x over previous
#include <cuda_runtime.h>
#include <cstdint>

#define NN 100000
#define EE 1600000
#define FIN 32
#define HD 128
#define SCAN_B 98   // ceil(NN/1024)

// ---------------- persistent device scratch (no allocs allowed) ----------------
__device__ float g_bufA[(size_t)NN * HD];
__device__ float g_bufB[(size_t)NN * HD];
__device__ float g_agg [(size_t)NN * HD];
__device__ int   g_deg[NN];
__device__ int   g_rowptr[NN + 1];
__device__ int   g_pos[NN];
__device__ int   g_col[EE];
__device__ int   g_bsum[SCAN_B];
__device__ int   g_is64;

// ---------------- edge-index dtype detection (int64 vs int32) ----------------
__global__ void k_detect(const void* ei) {
    __shared__ int s_nz;
    if (threadIdx.x == 0) s_nz = 0;
    __syncthreads();
    const int* p = (const int*)ei;
    for (int i = threadIdx.x; i < 8192; i += blockDim.x) {
        if (p[2 * i + 1] != 0) s_nz = 1;
    }
    __syncthreads();
    if (threadIdx.x == 0) g_is64 = (s_nz == 0) ? 1 : 0;
}

__device__ __forceinline__ int edge_at(const void* ei, long long idx) {
    if (g_is64) return (int)((const long long*)ei)[idx];
    return ((const int*)ei)[idx];
}

// ---------------- CSR build ----------------
__global__ void k_zero_deg() {
    int i = blockIdx.x * blockDim.x + threadIdx.x;
    if (i < NN) g_deg[i] = 0;
}

__global__ void k_count(const void* ei) {
    int e = blockIdx.x * blockDim.x + threadIdx.x;
    if (e >= EE) return;
    atomicAdd(&g_deg[edge_at(ei, (long long)EE + e)], 1);
}

// phase 1: per-block (1024 elems) sums
__global__ void k_scan1() {
    __shared__ int wsum[32];
    int i = blockIdx.x * 1024 + threadIdx.x;
    int v = (i < NN) ? g_deg[i] : 0;
    int lane = threadIdx.x & 31, w = threadIdx.x >> 5;
#pragma unroll
    for (int o = 16; o; o >>= 1) v += __shfl_xor_sync(0xFFFFFFFFu, v, o);
    if (lane == 0) wsum[w] = v;
    __syncthreads();
    if (w == 0) {
        int s = wsum[lane];
#pragma unroll
        for (int o = 16; o; o >>= 1) s += __shfl_xor_sync(0xFFFFFFFFu, s, o);
        if (lane == 0) g_bsum[blockIdx.x] = s;
    }
}

// phase 2: exclusive scan of block sums (tiny)
__global__ void k_scan2() {
    if (threadIdx.x == 0) {
        int run = 0;
        for (int i = 0; i < SCAN_B; i++) { int t = g_bsum[i]; g_bsum[i] = run; run += t; }
        g_rowptr[NN] = run;
    }
}

// phase 3: per-block exclusive scan + add block offset
__global__ void k_scan3() {
    __shared__ int wsum[32];
    int b = blockIdx.x, tid = threadIdx.x;
    int i = b * 1024 + tid;
    int v = (i < NN) ? g_deg[i] : 0;
    int lane = tid & 31, w = tid >> 5;
    int x = v;
#pragma unroll
    for (int o = 1; o < 32; o <<= 1) {
        int t = __shfl_up_sync(0xFFFFFFFFu, x, o);
        if (lane >= o) x += t;
    }
    if (lane == 31) wsum[w] = x;
    __syncthreads();
    if (w == 0) {
        int s = wsum[lane];
#pragma unroll
        for (int o = 1; o < 32; o <<= 1) {
            int t = __shfl_up_sync(0xFFFFFFFFu, s, o);
            if (lane >= o) s += t;
        }
        wsum[lane] = s;
    }
    __syncthreads();
    int off = (w > 0) ? wsum[w - 1] : 0;
    int excl = x + off + g_bsum[b] - v;
    if (i < NN) { g_rowptr[i] = excl; g_pos[i] = excl; }
}

__global__ void k_fill(const void* ei) {
    int e = blockIdx.x * blockDim.x + threadIdx.x;
    if (e >= EE) return;
    int s = edge_at(ei, e);
    int d = edge_at(ei, (long long)EE + e);
    int p = atomicAdd(&g_pos[d], 1);
    g_col[p] = s;
}

// ---------------- mean aggregation: warp per node, CSR gather ----------------
template <int DIM>
__global__ void k_aggregate(const float* __restrict__ hin, float* __restrict__ agg) {
    int w = (blockIdx.x * blockDim.x + threadIdx.x) >> 5;
    int lane = threadIdx.x & 31;
    if (w >= NN) return;
    int beg = g_rowptr[w], end = g_rowptr[w + 1];
    float inv = 1.f / fmaxf((float)(end - beg), 1.f);
    if (DIM == 128) {
        float ax = 0.f, ay = 0.f, az = 0.f, aw = 0.f;
        for (int e = beg; e < end; e++) {
            int s = g_col[e];
            float4 v = *(const float4*)(hin + (size_t)s * 128 + lane * 4);
            ax += v.x; ay += v.y; az += v.z; aw += v.w;
        }
        float4 o; o.x = ax * inv; o.y = ay * inv; o.z = az * inv; o.w = aw * inv;
        *(float4*)(agg + (size_t)w * 128 + lane * 4) = o;
    } else {
        float a = 0.f;
        for (int e = beg; e < end; e++)
            a += hin[(size_t)g_col[e] * DIM + lane];
        agg[(size_t)w * DIM + lane] = a * inv;
    }
}

// ---------------- TF32 helpers ----------------
__device__ __forceinline__ float tf32r(float x) {
    uint32_t u;
    asm("cvt.rna.tf32.f32 %0, %1;" : "=r"(u) : "f"(x));
    return __uint_as_float(u);
}

__device__ __forceinline__ void mma8(float* c,
    uint32_t a0, uint32_t a1, uint32_t a2, uint32_t a3,
    uint32_t b0, uint32_t b1)
{
    asm volatile(
        "mma.sync.aligned.m16n8k8.row.col.f32.tf32.tf32.f32 "
        "{%0,%1,%2,%3}, {%4,%5,%6,%7}, {%8,%9}, {%0,%1,%2,%3};"
        : "+f"(c[0]), "+f"(c[1]), "+f"(c[2]), "+f"(c[3])
        : "r"(a0), "r"(a1), "r"(a2), "r"(a3), "r"(b0), "r"(b1));
}

// ---------------- fused GEMM (+bias) [+ LayerNorm+ReLU+residual [+ head]] -----
// out[N,128] = concat(A1,A2)[N,Ktot] @ concat(W1;W2)[Ktot,128] + bias
// MODE 0: raw write. MODE 1: relu(LN(.))+res. MODE 2: MODE1 + y = h@Wh + bh.
// 3-term TF32 split precision (hi*hi + hi*lo + lo*hi) -> ~fp32 accuracy.
// Block: 128 nodes x 128 cols, 256 threads (8 warps as 2x4), 8x8 mma tiling.
template <int MODE>
__global__ __launch_bounds__(256) void k_mma_gemm(
    const float* __restrict__ A1, const float* __restrict__ A2,
    int kin, int Ktot,
    const float* __restrict__ W1, const float* __restrict__ W2,
    const float* __restrict__ bias,
    const float* __restrict__ gamma, const float* __restrict__ beta,
    const float* __restrict__ res,
    float* __restrict__ out,
    const float* __restrict__ Wh, const float* __restrict__ bh,
    float* __restrict__ y)
{
    __shared__ float sAh[16][132], sAl[16][132];
    __shared__ float sWh[16][132], sWl[16][132];
    __shared__ float s_sum[4][128], s_sq[4][128];
    __shared__ float s_mu[128], s_rstd[128], s_y[128];

    const int tid = threadIdx.x;
    const int lane = tid & 31, wid = tid >> 5;
    const int wm = wid >> 2, wn = wid & 3;       // 2 x 4 warp grid
    const int g = lane >> 2, tig = lane & 3;
    const int node0 = blockIdx.x * 128;

    float acc[4][4][4];
#pragma unroll
    for (int mt = 0; mt < 4; mt++)
#pragma unroll
        for (int nt = 0; nt < 4; nt++)
#pragma unroll
            for (int i = 0; i < 4; i++) acc[mt][nt][i] = 0.f;

    for (int k0 = 0; k0 < Ktot; k0 += 16) {
        const float* Asrc; const float* Wsrc; int koff;
        if (k0 < kin) { Asrc = A1; Wsrc = W1; koff = k0; }
        else          { Asrc = A2; Wsrc = W2; koff = k0 - kin; }

        // stage A transposed (hi/lo): 128 rows x 16 k
#pragma unroll
        for (int q = 0; q < 2; q++) {
            int f = tid + q * 256;
            int row = f >> 2, kq = (f & 3) * 4;
            float4 v = make_float4(0.f, 0.f, 0.f, 0.f);
            int node = node0 + row;
            if (node < NN) v = *(const float4*)(Asrc + (size_t)node * kin + koff + kq);
            float hx = tf32r(v.x), hy = tf32r(v.y), hz = tf32r(v.z), hw = tf32r(v.w);
            sAh[kq + 0][row] = hx;          sAl[kq + 0][row] = tf32r(v.x - hx);
            sAh[kq + 1][row] = hy;          sAl[kq + 1][row] = tf32r(v.y - hy);
            sAh[kq + 2][row] = hz;          sAl[kq + 2][row] = tf32r(v.z - hz);
            sAh[kq + 3][row] = hw;          sAl[kq + 3][row] = tf32r(v.w - hw);
        }
        // stage W (hi/lo): 16 k x 128 cols
#pragma unroll
        for (int q = 0; q < 2; q++) {
            int f = tid + q * 256;
            int wr = f >> 5, wc = (f & 31) * 4;
            float4 v = *(const float4*)(Wsrc + (size_t)(koff + wr) * HD + wc);
            float4 h4, l4;
            h4.x = tf32r(v.x); l4.x = tf32r(v.x - h4.x);
            h4.y = tf32r(v.y); l4.y = tf32r(v.y - h4.y);
            h4.z = tf32r(v.z); l4.z = tf32r(v.z - h4.z);
            h4.w = tf32r(v.w); l4.w = tf32r(v.w - h4.w);
            *(float4*)&sWh[wr][wc] = h4;
            *(float4*)&sWl[wr][wc] = l4;
        }
        __syncthreads();

#pragma unroll
        for (int ks = 0; ks < 2; ks++) {
            int kb = ks * 8;
            uint32_t bh0[4], bh1[4], bl0[4], bl1[4];
#pragma unroll
            for (int nt = 0; nt < 4; nt++) {
                int n = wn * 32 + nt * 8 + g;
                bh0[nt] = __float_as_uint(sWh[kb + tig][n]);
                bh1[nt] = __float_as_uint(sWh[kb + tig + 4][n]);
                bl0[nt] = __float_as_uint(sWl[kb + tig][n]);
                bl1[nt] = __float_as_uint(sWl[kb + tig + 4][n]);
            }
#pragma unroll
            for (int mt = 0; mt < 4; mt++) {
                int r = wm * 64 + mt * 16 + g;
                uint32_t a0h = __float_as_uint(sAh[kb + tig][r]);
                uint32_t a1h = __float_as_uint(sAh[kb + tig][r + 8]);
                uint32_t a2h = __float_as_uint(sAh[kb + tig + 4][r]);
                uint32_t a3h = __float_as_uint(sAh[kb + tig + 4][r + 8]);
                uint32_t a0l = __float_as_uint(sAl[kb + tig][r]);
                uint32_t a1l = __float_as_uint(sAl[kb + tig][r + 8]);
                uint32_t a2l = __float_as_uint(sAl[kb + tig + 4][r]);
                uint32_t a3l = __float_as_uint(sAl[kb + tig + 4][r + 8]);
#pragma unroll
                for (int nt = 0; nt < 4; nt++) {
                    mma8(acc[mt][nt], a0h, a1h, a2h, a3h, bh0[nt], bh1[nt]);
                    mma8(acc[mt][nt], a0h, a1h, a2h, a3h, bl0[nt], bl1[nt]);
                    mma8(acc[mt][nt], a0l, a1l, a2l, a3l, bh0[nt], bh1[nt]);
                }
            }
        }
        __syncthreads();
    }

    if (MODE == 0) {
#pragma unroll
        for (int mt = 0; mt < 4; mt++) {
            int r0 = wm * 64 + mt * 16 + g;
            int n0 = node0 + r0, n1 = n0 + 8;
#pragma unroll
            for (int nt = 0; nt < 4; nt++) {
                int c0 = wn * 32 + nt * 8 + tig * 2;
                float bx = 0.f, by = 0.f;
                if (bias) { float2 b2 = *(const float2*)(bias + c0); bx = b2.x; by = b2.y; }
                if (n0 < NN) {
                    float2 o0 = make_float2(acc[mt][nt][0] + bx, acc[mt][nt][1] + by);
                    *(float2*)(out + (size_t)n0 * HD + c0) = o0;
                }
                if (n1 < NN) {
                    float2 o1 = make_float2(acc[mt][nt][2] + bx, acc[mt][nt][3] + by);
                    *(float2*)(out + (size_t)n1 * HD + c0) = o1;
                }
            }
        }
        return;
    }

    // ---- bias add (pre-LN) ----
#pragma unroll
    for (int mt = 0; mt < 4; mt++)
#pragma unroll
        for (int nt = 0; nt < 4; nt++) {
            int c0 = wn * 32 + nt * 8 + tig * 2;
            float2 b2 = *(const float2*)(bias + c0);
            acc[mt][nt][0] += b2.x; acc[mt][nt][1] += b2.y;
            acc[mt][nt][2] += b2.x; acc[mt][nt][3] += b2.y;
        }

    // ---- row partial sums for LN ----
#pragma unroll
    for (int mt = 0; mt < 4; mt++) {
        float s0 = 0.f, q0 = 0.f, s1 = 0.f, q1 = 0.f;
#pragma unroll
        for (int nt = 0; nt < 4; nt++) {
            float a0 = acc[mt][nt][0], a1 = acc[mt][nt][1];
            float a2 = acc[mt][nt][2], a3 = acc[mt][nt][3];
            s0 += a0 + a1; q0 += a0 * a0 + a1 * a1;
            s1 += a2 + a3; q1 += a2 * a2 + a3 * a3;
        }
#pragma unroll
        for (int o = 1; o < 4; o <<= 1) {
            s0 += __shfl_xor_sync(0xFFFFFFFFu, s0, o);
            q0 += __shfl_xor_sync(0xFFFFFFFFu, q0, o);
            s1 += __shfl_xor_sync(0xFFFFFFFFu, s1, o);
            q1 += __shfl_xor_sync(0xFFFFFFFFu, q1, o);
        }
        if (tig == 0) {
            int r0 = wm * 64 + mt * 16 + g;
            s_sum[wn][r0] = s0; s_sq[wn][r0] = q0;
            s_sum[wn][r0 + 8] = s1; s_sq[wn][r0 + 8] = q1;
        }
    }
    __syncthreads();
    if (tid < 128) {
        float s = s_sum[0][tid] + s_sum[1][tid] + s_sum[2][tid] + s_sum[3][tid];
        float q = s_sq[0][tid] + s_sq[1][tid] + s_sq[2][tid] + s_sq[3][tid];
        float mu = s * (1.f / 128.f);
        float var = q * (1.f / 128.f) - mu * mu;
        s_mu[tid] = mu;
        s_rstd[tid] = rsqrtf(var + 1e-5f);
        if (MODE == 2) s_y[tid] = 0.f;
    }
    __syncthreads();

    // ---- apply LN + relu + residual (+ head) ----
#pragma unroll
    for (int mt = 0; mt < 4; mt++) {
        int r0 = wm * 64 + mt * 16 + g, r1 = r0 + 8;
        int n0 = node0 + r0, n1 = node0 + r1;
        float mu0 = s_mu[r0], rs0 = s_rstd[r0];
        float mu1 = s_mu[r1], rs1 = s_rstd[r1];
        float y0 = 0.f, y1 = 0.f;
#pragma unroll
        for (int nt = 0; nt < 4; nt++) {
            int c0 = wn * 32 + nt * 8 + tig * 2;
            float2 g2 = *(const float2*)(gamma + c0);
            float2 b2 = *(const float2*)(beta + c0);
            float v00 = fmaxf((acc[mt][nt][0] - mu0) * rs0 * g2.x + b2.x, 0.f);
            float v01 = fmaxf((acc[mt][nt][1] - mu0) * rs0 * g2.y + b2.y, 0.f);
            float v10 = fmaxf((acc[mt][nt][2] - mu1) * rs1 * g2.x + b2.x, 0.f);
            float v11 = fmaxf((acc[mt][nt][3] - mu1) * rs1 * g2.y + b2.y, 0.f);
            if (n0 < NN) {
                float2 r2 = *(const float2*)(res + (size_t)n0 * HD + c0);
                v00 += r2.x; v01 += r2.y;
                *(float2*)(out + (size_t)n0 * HD + c0) = make_float2(v00, v01);
            }
            if (n1 < NN) {
                float2 r2 = *(const float2*)(res + (size_t)n1 * HD + c0);
                v10 += r2.x; v11 += r2.y;
                *(float2*)(out + (size_t)n1 * HD + c0) = make_float2(v10, v11);
            }
            if (MODE == 2) {
                float2 w2 = *(const float2*)(Wh + c0);
                y0 += v00 * w2.x + v01 * w2.y;
                y1 += v10 * w2.x + v11 * w2.y;
            }
        }
        if (MODE == 2) {
#pragma unroll
            for (int o = 1; o < 4; o <<= 1) {
                y0 += __shfl_xor_sync(0xFFFFFFFFu, y0, o);
                y1 += __shfl_xor_sync(0xFFFFFFFFu, y1, o);
            }
            if (tig == 0) {
                atomicAdd(&s_y[r0], y0);
                atomicAdd(&s_y[r1], y1);
            }
        }
    }
    if (MODE == 2) {
        __syncthreads();
        if (tid < 128 && node0 + tid < NN)
            y[node0 + tid] = s_y[tid] + bh[0];
    }
}

// ---------------- launcher ----------------
extern "C" void kernel_launch(void* const* d_in, const int* in_sizes, int n_in,
                              void* d_out, int out_size)
{
    const float* x     = (const float*)d_in[0];
    const void*  ei    = d_in[1];
    const float* Wl0   = (const float*)d_in[2];
    const float* bl0   = (const float*)d_in[3];
    const float* Wr0   = (const float*)d_in[4];
    const float* g0    = (const float*)d_in[5];
    const float* be0   = (const float*)d_in[6];
    const float* Wl1   = (const float*)d_in[7];
    const float* bl1   = (const float*)d_in[8];
    const float* Wr1   = (const float*)d_in[9];
    const float* g1    = (const float*)d_in[10];
    const float* be1   = (const float*)d_in[11];
    const float* Wl2   = (const float*)d_in[12];
    const float* bl2   = (const float*)d_in[13];
    const float* Wr2   = (const float*)d_in[14];
    const float* g2    = (const float*)d_in[15];
    const float* be2   = (const float*)d_in[16];
    const float* Wproj = (const float*)d_in[17];
    const float* Wh    = (const float*)d_in[18];
    const float* bh    = (const float*)d_in[19];

    float* out = (float*)d_out;

    float *pA, *pB, *pAgg;
    cudaGetSymbolAddress((void**)&pA,   g_bufA);
    cudaGetSymbolAddress((void**)&pB,   g_bufB);
    cudaGetSymbolAddress((void**)&pAgg, g_agg);

    float* hout = (out_size >= NN + NN * HD) ? (out + NN) : pA;

    const int TB = 256;
    dim3 gN((NN + TB - 1) / TB), gE((EE + TB - 1) / TB);
    dim3 gWarp((NN + 7) / 8);
    dim3 gGemm((NN + 127) / 128);

    // CSR build
    k_detect<<<1, 256>>>(ei);
    k_zero_deg<<<gN, TB>>>();
    k_count<<<gE, TB>>>(ei);
    k_scan1<<<SCAN_B, 1024>>>();
    k_scan2<<<1, 32>>>();
    k_scan3<<<SCAN_B, 1024>>>();
    k_fill<<<gE, TB>>>(ei);

    // ---- layer 0 ----
    k_aggregate<FIN><<<gWarp, TB>>>(x, pAgg);
    // proj = x @ Wproj (raw)
    k_mma_gemm<0><<<gGemm, TB>>>(x, x, FIN, FIN, Wproj, Wproj, nullptr,
                                 nullptr, nullptr, nullptr, pB, nullptr, nullptr, nullptr);
    // h0 = relu(LN([agg|x] @ [Wl0;Wr0] + bl0)) + proj
    k_mma_gemm<1><<<gGemm, TB>>>(pAgg, x, FIN, 2 * FIN, Wl0, Wr0, bl0,
                                 g0, be0, pB, pA, nullptr, nullptr, nullptr);

    // ---- layer 1 ----
    k_aggregate<HD><<<gWarp, TB>>>(pA, pAgg);
    k_mma_gemm<1><<<gGemm, TB>>>(pAgg, pA, HD, 2 * HD, Wl1, Wr1, bl1,
                                 g1, be1, pA, pB, nullptr, nullptr, nullptr);

    // ---- layer 2 (+ fused head) ----
    k_aggregate<HD><<<gWarp, TB>>>(pB, pAgg);
    k_mma_gemm<2><<<gGemm, TB>>>(pAgg, pB, HD, 2 * HD, Wl2, Wr2, bl2,
                                 g2, be2, pB, hout, Wh, bh, out);
}

// round 3
// speedup vs baseline: 2.2478x; 1.2370x over previous
#include <cuda_runtime.h>
#include <cuda_bf16.h>
#include <cstdint>

#define NN 100000
#define EE 1600000
#define FIN 32
#define HD 128
#define SCAN_B 98   // ceil(NN/1024)

// ---------------- persistent device scratch (no allocs allowed) ----------------
__device__ float g_bufA[(size_t)NN * HD];
__device__ float g_bufB[(size_t)NN * HD];
__device__ float g_agg [(size_t)NN * HD];
__device__ int   g_deg[NN];
__device__ int   g_rowptr[NN + 1];
__device__ int   g_pos[NN];
__device__ int   g_col[EE];
__device__ int   g_bsum[SCAN_B];
__device__ int   g_is64;

// packed bf16x2 (hi,lo) weights, layout [kp][col] with kp = k/2, 128 cols
__device__ unsigned g_w0h[32 * 128],  g_w0l[32 * 128];   // layer0: Ktot=64
__device__ unsigned g_wph[16 * 128],  g_wpl[16 * 128];   // proj:   Ktot=32
__device__ unsigned g_w1h[128 * 128], g_w1l[128 * 128];  // layer1: Ktot=256
__device__ unsigned g_w2h[128 * 128], g_w2l[128 * 128];  // layer2: Ktot=256

// ---------------- bf16 helpers ----------------
__device__ __forceinline__ unsigned packbf(float lo, float hi) {
    unsigned d;
    asm("cvt.rn.bf16x2.f32 %0, %1, %2;" : "=r"(d) : "f"(hi), "f"(lo));
    return d;
}
__device__ __forceinline__ float ubf_lo(unsigned p) { return __uint_as_float(p << 16); }
__device__ __forceinline__ float ubf_hi(unsigned p) { return __uint_as_float(p & 0xFFFF0000u); }

__device__ __forceinline__ void mma16(float* c,
    unsigned a0, unsigned a1, unsigned a2, unsigned a3,
    unsigned b0, unsigned b1)
{
    asm volatile(
        "mma.sync.aligned.m16n8k16.row.col.f32.bf16.bf16.f32 "
        "{%0,%1,%2,%3}, {%4,%5,%6,%7}, {%8,%9}, {%0,%1,%2,%3};"
        : "+f"(c[0]), "+f"(c[1]), "+f"(c[2]), "+f"(c[3])
        : "r"(a0), "r"(a1), "r"(a2), "r"(a3), "r"(b0), "r"(b1));
}

// ---------------- edge-index dtype detection (int64 vs int32) ----------------
__global__ void k_detect(const void* ei) {
    __shared__ int s_nz;
    if (threadIdx.x == 0) s_nz = 0;
    __syncthreads();
    const int* p = (const int*)ei;
    for (int i = threadIdx.x; i < 8192; i += blockDim.x) {
        if (p[2 * i + 1] != 0) s_nz = 1;
    }
    __syncthreads();
    if (threadIdx.x == 0) g_is64 = (s_nz == 0) ? 1 : 0;
}

__device__ __forceinline__ int edge_at(const void* ei, long long idx) {
    if (g_is64) return (int)((const long long*)ei)[idx];
    return ((const int*)ei)[idx];
}

// ---------------- weight prep: fp32 -> packed bf16x2 hi/lo ----------------
__global__ void k_wprep(const float* __restrict__ W1, const float* __restrict__ W2,
                        int kin, int Ktot, unsigned* __restrict__ oh, unsigned* __restrict__ ol)
{
    int idx = blockIdx.x * blockDim.x + threadIdx.x;
    int total = (Ktot / 2) * 128;
    if (idx >= total) return;
    int kp = idx >> 7, col = idx & 127;
    int k = 2 * kp;
    const float* W = (k < kin) ? W1 : W2;
    int kk = (k < kin) ? k : (k - kin);
    float v0 = W[(size_t)kk * HD + col];
    float v1 = W[(size_t)(kk + 1) * HD + col];
    unsigned hp = packbf(v0, v1);
    float l0 = v0 - ubf_lo(hp);
    float l1 = v1 - ubf_hi(hp);
    oh[idx] = hp;
    ol[idx] = packbf(l0, l1);
}

// ---------------- CSR build ----------------
__global__ void k_zero_deg() {
    int i = blockIdx.x * blockDim.x + threadIdx.x;
    if (i < NN) g_deg[i] = 0;
}

__global__ void k_count(const void* ei) {
    int e = blockIdx.x * blockDim.x + threadIdx.x;
    if (e >= EE) return;
    atomicAdd(&g_deg[edge_at(ei, (long long)EE + e)], 1);
}

__global__ void k_scan1() {
    __shared__ int wsum[32];
    int i = blockIdx.x * 1024 + threadIdx.x;
    int v = (i < NN) ? g_deg[i] : 0;
    int lane = threadIdx.x & 31, w = threadIdx.x >> 5;
#pragma unroll
    for (int o = 16; o; o >>= 1) v += __shfl_xor_sync(0xFFFFFFFFu, v, o);
    if (lane == 0) wsum[w] = v;
    __syncthreads();
    if (w == 0) {
        int s = wsum[lane];
#pragma unroll
        for (int o = 16; o; o >>= 1) s += __shfl_xor_sync(0xFFFFFFFFu, s, o);
        if (lane == 0) g_bsum[blockIdx.x] = s;
    }
}

__global__ void k_scan2() {
    if (threadIdx.x == 0) {
        int run = 0;
        for (int i = 0; i < SCAN_B; i++) { int t = g_bsum[i]; g_bsum[i] = run; run += t; }
        g_rowptr[NN] = run;
    }
}

__global__ void k_scan3() {
    __shared__ int wsum[32];
    int b = blockIdx.x, tid = threadIdx.x;
    int i = b * 1024 + tid;
    int v = (i < NN) ? g_deg[i] : 0;
    int lane = tid & 31, w = tid >> 5;
    int x = v;
#pragma unroll
    for (int o = 1; o < 32; o <<= 1) {
        int t = __shfl_up_sync(0xFFFFFFFFu, x, o);
        if (lane >= o) x += t;
    }
    if (lane == 31) wsum[w] = x;
    __syncthreads();
    if (w == 0) {
        int s = wsum[lane];
#pragma unroll
        for (int o = 1; o < 32; o <<= 1) {
            int t = __shfl_up_sync(0xFFFFFFFFu, s, o);
            if (lane >= o) s += t;
        }
        wsum[lane] = s;
    }
    __syncthreads();
    int off = (w > 0) ? wsum[w - 1] : 0;
    int excl = x + off + g_bsum[b] - v;
    if (i < NN) { g_rowptr[i] = excl; g_pos[i] = excl; }
}

__global__ void k_fill(const void* ei) {
    int e = blockIdx.x * blockDim.x + threadIdx.x;
    if (e >= EE) return;
    int s = edge_at(ei, e);
    int d = edge_at(ei, (long long)EE + e);
    int p = atomicAdd(&g_pos[d], 1);
    g_col[p] = s;
}

// ---------------- mean aggregation: warp per node, CSR gather, unroll 4 -------
template <int DIM>
__global__ void k_aggregate(const float* __restrict__ hin, float* __restrict__ agg) {
    int w = (blockIdx.x * blockDim.x + threadIdx.x) >> 5;
    int lane = threadIdx.x & 31;
    if (w >= NN) return;
    int beg = g_rowptr[w], end = g_rowptr[w + 1];
    float inv = 1.f / fmaxf((float)(end - beg), 1.f);
    if (DIM == 128) {
        float ax = 0.f, ay = 0.f, az = 0.f, aw = 0.f;
        int e = beg;
        for (; e + 4 <= end; e += 4) {
            int s0 = g_col[e], s1 = g_col[e + 1], s2 = g_col[e + 2], s3 = g_col[e + 3];
            float4 v0 = *(const float4*)(hin + (size_t)s0 * 128 + lane * 4);
            float4 v1 = *(const float4*)(hin + (size_t)s1 * 128 + lane * 4);
            float4 v2 = *(const float4*)(hin + (size_t)s2 * 128 + lane * 4);
            float4 v3 = *(const float4*)(hin + (size_t)s3 * 128 + lane * 4);
            ax += v0.x + v1.x + v2.x + v3.x;
            ay += v0.y + v1.y + v2.y + v3.y;
            az += v0.z + v1.z + v2.z + v3.z;
            aw += v0.w + v1.w + v2.w + v3.w;
        }
        for (; e < end; e++) {
            float4 v = *(const float4*)(hin + (size_t)g_col[e] * 128 + lane * 4);
            ax += v.x; ay += v.y; az += v.z; aw += v.w;
        }
        float4 o; o.x = ax * inv; o.y = ay * inv; o.z = az * inv; o.w = aw * inv;
        *(float4*)(agg + (size_t)w * 128 + lane * 4) = o;
    } else {
        float a = 0.f;
        int e = beg;
        for (; e + 4 <= end; e += 4) {
            int s0 = g_col[e], s1 = g_col[e + 1], s2 = g_col[e + 2], s3 = g_col[e + 3];
            a += hin[(size_t)s0 * DIM + lane] + hin[(size_t)s1 * DIM + lane]
               + hin[(size_t)s2 * DIM + lane] + hin[(size_t)s3 * DIM + lane];
        }
        for (; e < end; e++)
            a += hin[(size_t)g_col[e] * DIM + lane];
        agg[(size_t)w * DIM + lane] = a * inv;
    }
}

// ---------------- fused bf16x3 GEMM (+bias) [+ LN+ReLU+res [+ head]] ---------
// out[N,128] = concat(A1,A2)[N,Ktot] @ Wpacked[Ktot,128] + bias
// MODE 0: raw write. MODE 1: relu(LN(.))+res. MODE 2: MODE1 + y = h@Wh + bh.
// Split precision: x=xh+xl, w=wh+wl (bf16) -> xh*wh + xh*wl + xl*wh, fp32 acc.
// Block: 128 nodes x 128 cols, 256 threads (2x4 warps), m16n8k16 mma.
template <int MODE>
__global__ __launch_bounds__(256, 2) void k_mma_gemm(
    const float* __restrict__ A1, const float* __restrict__ A2,
    int kin, int Ktot,
    const unsigned* __restrict__ Wph, const unsigned* __restrict__ Wpl,
    const float* __restrict__ bias,
    const float* __restrict__ gamma, const float* __restrict__ beta,
    const float* __restrict__ res,
    float* __restrict__ out,
    const float* __restrict__ Wh, const float* __restrict__ bh,
    float* __restrict__ y)
{
    __shared__ unsigned sAh[8][132], sAl[8][132];
    __shared__ unsigned sWh[8][132], sWl[8][132];
    __shared__ float s_sum[4][128], s_sq[4][128];
    __shared__ float s_mu[128], s_rstd[128], s_y[128];

    const int tid = threadIdx.x;
    const int lane = tid & 31, wid = tid >> 5;
    const int wm = wid >> 2, wn = wid & 3;       // 2 x 4 warp grid
    const int g = lane >> 2, tig = lane & 3;
    const int node0 = blockIdx.x * 128;

    float acc[4][4][4];
#pragma unroll
    for (int mt = 0; mt < 4; mt++)
#pragma unroll
        for (int nt = 0; nt < 4; nt++)
#pragma unroll
            for (int i = 0; i < 4; i++) acc[mt][nt][i] = 0.f;

    // staging indices
    const int arow = tid >> 2;                 // A: rows tid>>2 and +64
    const int aq   = tid & 3;                  // which float4 (k = 4q..4q+3)
    const int wrow = tid >> 5;                 // W: kp row 0..7
    const int wcol = (tid & 31) * 4;

    for (int k0 = 0; k0 < Ktot; k0 += 16) {
        const float* Asrc; int koff;
        if (k0 < kin) { Asrc = A1; koff = k0; } else { Asrc = A2; koff = k0 - kin; }
        const int kp0 = k0 >> 1;

        // stage A (hi/lo packed bf16x2, transposed: [kp][row])
#pragma unroll
        for (int h = 0; h < 2; h++) {
            int row = arow + h * 64;
            int node = node0 + row;
            float4 v = make_float4(0.f, 0.f, 0.f, 0.f);
            if (node < NN) v = *(const float4*)(Asrc + (size_t)node * kin + koff + aq * 4);
            unsigned hp0 = packbf(v.x, v.y);
            unsigned hp1 = packbf(v.z, v.w);
            unsigned lp0 = packbf(v.x - ubf_lo(hp0), v.y - ubf_hi(hp0));
            unsigned lp1 = packbf(v.z - ubf_lo(hp1), v.w - ubf_hi(hp1));
            sAh[2 * aq][row] = hp0; sAh[2 * aq + 1][row] = hp1;
            sAl[2 * aq][row] = lp0; sAl[2 * aq + 1][row] = lp1;
        }
        // stage W (already packed): 8 kp rows x 128 cols, uint4 per thread
        {
            const unsigned* src = Wph + (size_t)(kp0 + wrow) * 128 + wcol;
            *(uint4*)&sWh[wrow][wcol] = *(const uint4*)src;
            const unsigned* srl = Wpl + (size_t)(kp0 + wrow) * 128 + wcol;
            *(uint4*)&sWl[wrow][wcol] = *(const uint4*)srl;
        }
        __syncthreads();

        unsigned bh0[4], bh1[4], bl0[4], bl1[4];
#pragma unroll
        for (int nt = 0; nt < 4; nt++) {
            int n = wn * 32 + nt * 8 + g;
            bh0[nt] = sWh[tig][n];     bh1[nt] = sWh[tig + 4][n];
            bl0[nt] = sWl[tig][n];     bl1[nt] = sWl[tig + 4][n];
        }
#pragma unroll
        for (int mt = 0; mt < 4; mt++) {
            int r = wm * 64 + mt * 16 + g;
            unsigned a0h = sAh[tig][r],     a1h = sAh[tig][r + 8];
            unsigned a2h = sAh[tig + 4][r], a3h = sAh[tig + 4][r + 8];
            unsigned a0l = sAl[tig][r],     a1l = sAl[tig][r + 8];
            unsigned a2l = sAl[tig + 4][r], a3l = sAl[tig + 4][r + 8];
#pragma unroll
            for (int nt = 0; nt < 4; nt++) {
                mma16(acc[mt][nt], a0h, a1h, a2h, a3h, bh0[nt], bh1[nt]);
                mma16(acc[mt][nt], a0h, a1h, a2h, a3h, bl0[nt], bl1[nt]);
                mma16(acc[mt][nt], a0l, a1l, a2l, a3l, bh0[nt], bh1[nt]);
            }
        }
        __syncthreads();
    }

    if (MODE == 0) {
#pragma unroll
        for (int mt = 0; mt < 4; mt++) {
            int r0 = wm * 64 + mt * 16 + g;
            int n0 = node0 + r0, n1 = n0 + 8;
#pragma unroll
            for (int nt = 0; nt < 4; nt++) {
                int c0 = wn * 32 + nt * 8 + tig * 2;
                float bx = 0.f, by = 0.f;
                if (bias) { float2 b2 = *(const float2*)(bias + c0); bx = b2.x; by = b2.y; }
                if (n0 < NN)
                    *(float2*)(out + (size_t)n0 * HD + c0) =
                        make_float2(acc[mt][nt][0] + bx, acc[mt][nt][1] + by);
                if (n1 < NN)
                    *(float2*)(out + (size_t)n1 * HD + c0) =
                        make_float2(acc[mt][nt][2] + bx, acc[mt][nt][3] + by);
            }
        }
        return;
    }

    // ---- bias add (pre-LN) ----
#pragma unroll
    for (int mt = 0; mt < 4; mt++)
#pragma unroll
        for (int nt = 0; nt < 4; nt++) {
            int c0 = wn * 32 + nt * 8 + tig * 2;
            float2 b2 = *(const float2*)(bias + c0);
            acc[mt][nt][0] += b2.x; acc[mt][nt][1] += b2.y;
            acc[mt][nt][2] += b2.x; acc[mt][nt][3] += b2.y;
        }

    // ---- row partial sums for LN ----
#pragma unroll
    for (int mt = 0; mt < 4; mt++) {
        float s0 = 0.f, q0 = 0.f, s1 = 0.f, q1 = 0.f;
#pragma unroll
        for (int nt = 0; nt < 4; nt++) {
            float a0 = acc[mt][nt][0], a1 = acc[mt][nt][1];
            float a2 = acc[mt][nt][2], a3 = acc[mt][nt][3];
            s0 += a0 + a1; q0 += a0 * a0 + a1 * a1;
            s1 += a2 + a3; q1 += a2 * a2 + a3 * a3;
        }
#pragma unroll
        for (int o = 1; o < 4; o <<= 1) {
            s0 += __shfl_xor_sync(0xFFFFFFFFu, s0, o);
            q0 += __shfl_xor_sync(0xFFFFFFFFu, q0, o);
            s1 += __shfl_xor_sync(0xFFFFFFFFu, s1, o);
            q1 += __shfl_xor_sync(0xFFFFFFFFu, q1, o);
        }
        if (tig == 0) {
            int r0 = wm * 64 + mt * 16 + g;
            s_sum[wn][r0] = s0;     s_sq[wn][r0] = q0;
            s_sum[wn][r0 + 8] = s1; s_sq[wn][r0 + 8] = q1;
        }
    }
    __syncthreads();
    if (tid < 128) {
        float s = s_sum[0][tid] + s_sum[1][tid] + s_sum[2][tid] + s_sum[3][tid];
        float q = s_sq[0][tid] + s_sq[1][tid] + s_sq[2][tid] + s_sq[3][tid];
        float mu = s * (1.f / 128.f);
        float var = q * (1.f / 128.f) - mu * mu;
        s_mu[tid] = mu;
        s_rstd[tid] = rsqrtf(var + 1e-5f);
        if (MODE == 2) s_y[tid] = 0.f;
    }
    __syncthreads();

    // ---- apply LN + relu + residual (+ head) ----
#pragma unroll
    for (int mt = 0; mt < 4; mt++) {
        int r0 = wm * 64 + mt * 16 + g, r1 = r0 + 8;
        int n0 = node0 + r0, n1 = node0 + r1;
        float mu0 = s_mu[r0], rs0 = s_rstd[r0];
        float mu1 = s_mu[r1], rs1 = s_rstd[r1];
        float y0 = 0.f, y1 = 0.f;
#pragma unroll
        for (int nt = 0; nt < 4; nt++) {
            int c0 = wn * 32 + nt * 8 + tig * 2;
            float2 g2 = *(const float2*)(gamma + c0);
            float2 b2 = *(const float2*)(beta + c0);
            float v00 = fmaxf((acc[mt][nt][0] - mu0) * rs0 * g2.x + b2.x, 0.f);
            float v01 = fmaxf((acc[mt][nt][1] - mu0) * rs0 * g2.y + b2.y, 0.f);
            float v10 = fmaxf((acc[mt][nt][2] - mu1) * rs1 * g2.x + b2.x, 0.f);
            float v11 = fmaxf((acc[mt][nt][3] - mu1) * rs1 * g2.y + b2.y, 0.f);
            if (n0 < NN) {
                float2 r2 = *(const float2*)(res + (size_t)n0 * HD + c0);
                v00 += r2.x; v01 += r2.y;
                *(float2*)(out + (size_t)n0 * HD + c0) = make_float2(v00, v01);
            }
            if (n1 < NN) {
                float2 r2 = *(const float2*)(res + (size_t)n1 * HD + c0);
                v10 += r2.x; v11 += r2.y;
                *(float2*)(out + (size_t)n1 * HD + c0) = make_float2(v10, v11);
            }
            if (MODE == 2) {
                float2 w2 = *(const float2*)(Wh + c0);
                y0 += v00 * w2.x + v01 * w2.y;
                y1 += v10 * w2.x + v11 * w2.y;
            }
        }
        if (MODE == 2) {
#pragma unroll
            for (int o = 1; o < 4; o <<= 1) {
                y0 += __shfl_xor_sync(0xFFFFFFFFu, y0, o);
                y1 += __shfl_xor_sync(0xFFFFFFFFu, y1, o);
            }
            if (tig == 0) {
                atomicAdd(&s_y[r0], y0);
                atomicAdd(&s_y[r1], y1);
            }
        }
    }
    if (MODE == 2) {
        __syncthreads();
        if (tid < 128 && node0 + tid < NN)
            y[node0 + tid] = s_y[tid] + bh[0];
    }
}

// ---------------- launcher ----------------
extern "C" void kernel_launch(void* const* d_in, const int* in_sizes, int n_in,
                              void* d_out, int out_size)
{
    const float* x     = (const float*)d_in[0];
    const void*  ei    = d_in[1];
    const float* Wl0   = (const float*)d_in[2];
    const float* bl0   = (const float*)d_in[3];
    const float* Wr0   = (const float*)d_in[4];
    const float* g0    = (const float*)d_in[5];
    const float* be0   = (const float*)d_in[6];
    const float* Wl1   = (const float*)d_in[7];
    const float* bl1   = (const float*)d_in[8];
    const float* Wr1   = (const float*)d_in[9];
    const float* g1    = (const float*)d_in[10];
    const float* be1   = (const float*)d_in[11];
    const float* Wl2   = (const float*)d_in[12];
    const float* bl2   = (const float*)d_in[13];
    const float* Wr2   = (const float*)d_in[14];
    const float* g2    = (const float*)d_in[15];
    const float* be2   = (const float*)d_in[16];
    const float* Wproj = (const float*)d_in[17];
    const float* Wh    = (const float*)d_in[18];
    const float* bh    = (const float*)d_in[19];

    float* out = (float*)d_out;

    float *pA, *pB, *pAgg;
    cudaGetSymbolAddress((void**)&pA,   g_bufA);
    cudaGetSymbolAddress((void**)&pB,   g_bufB);
    cudaGetSymbolAddress((void**)&pAgg, g_agg);
    unsigned *w0h, *w0l, *wph, *wpl, *w1h, *w1l, *w2h, *w2l;
    cudaGetSymbolAddress((void**)&w0h, g_w0h); cudaGetSymbolAddress((void**)&w0l, g_w0l);
    cudaGetSymbolAddress((void**)&wph, g_wph); cudaGetSymbolAddress((void**)&wpl, g_wpl);
    cudaGetSymbolAddress((void**)&w1h, g_w1h); cudaGetSymbolAddress((void**)&w1l, g_w1l);
    cudaGetSymbolAddress((void**)&w2h, g_w2h); cudaGetSymbolAddress((void**)&w2l, g_w2l);

    float* hout = (out_size >= NN + NN * HD) ? (out + NN) : pA;

    const int TB = 256;
    dim3 gN((NN + TB - 1) / TB), gE((EE + TB - 1) / TB);
    dim3 gWarp((NN + 7) / 8);
    dim3 gGemm((NN + 127) / 128);

    // CSR build + weight prep
    k_detect<<<1, 256>>>(ei);
    k_zero_deg<<<gN, TB>>>();
    k_count<<<gE, TB>>>(ei);
    k_wprep<<<(32 * 128 + 255) / 256, 256>>>(Wl0, Wr0, FIN, 2 * FIN, w0h, w0l);
    k_wprep<<<(16 * 128 + 255) / 256, 256>>>(Wproj, Wproj, FIN, FIN, wph, wpl);
    k_wprep<<<(128 * 128 + 255) / 256, 256>>>(Wl1, Wr1, HD, 2 * HD, w1h, w1l);
    k_wprep<<<(128 * 128 + 255) / 256, 256>>>(Wl2, Wr2, HD, 2 * HD, w2h, w2l);
    k_scan1<<<SCAN_B, 1024>>>();
    k_scan2<<<1, 32>>>();
    k_scan3<<<SCAN_B, 1024>>>();
    k_fill<<<gE, TB>>>(ei);

    // ---- layer 0 ----
    k_aggregate<FIN><<<gWarp, TB>>>(x, pAgg);
    k_mma_gemm<0><<<gGemm, TB>>>(x, x, FIN, FIN, wph, wpl, nullptr,
                                 nullptr, nullptr, nullptr, pB, nullptr, nullptr, nullptr);
    k_mma_gemm<1><<<gGemm, TB>>>(pAgg, x, FIN, 2 * FIN, w0h, w0l, bl0,
                                 g0, be0, pB, pA, nullptr, nullptr, nullptr);

    // ---- layer 1 ----
    k_aggregate<HD><<<gWarp, TB>>>(pA, pAgg);
    k_mma_gemm<1><<<gGemm, TB>>>(pAgg, pA, HD, 2 * HD, w1h, w1l, bl1,
                                 g1, be1, pA, pB, nullptr, nullptr, nullptr);

    // ---- layer 2 (+ fused head) ----
    k_aggregate<HD><<<gWarp, TB>>>(pB, pAgg);
    k_mma_gemm<2><<<gGemm, TB>>>(pAgg, pB, HD, 2 * HD, w2h, w2l, bl2,
                                 g2, be2, pB, hout, Wh, bh, out);
}

// round 4
// speedup vs baseline: 2.3453x; 1.0434x over previous
#include <cuda_runtime.h>
#include <cuda_bf16.h>
#include <cuda_fp16.h>
#include <cstdint>

#define NN 100000
#define EE 1600000
#define FIN 32
#define HD 128
#define SCAN_B 98   // ceil(NN/1024)

// ---------------- persistent device scratch (no allocs allowed) ----------------
__device__ float g_bufA[(size_t)NN * HD];
__device__ float g_bufB[(size_t)NN * HD];
__device__ float g_agg [(size_t)NN * HD];
__device__ uint2 g_hh  [(size_t)NN * 32];   // fp16 mirror of current h (128 halves/row)
__device__ unsigned g_xh[(size_t)NN * 16];  // fp16 mirror of x (32 halves/row)
__device__ int   g_deg[NN];
__device__ int   g_rowptr[NN + 1];
__device__ int   g_pos[NN];
__device__ int   g_col[EE];
__device__ int   g_bsum[SCAN_B];
__device__ int   g_is64;

// packed bf16x2 (hi,lo) weights, layout [kp][col] with kp = k/2, 128 cols
__device__ unsigned g_w0h[32 * 128],  g_w0l[32 * 128];   // layer0: Ktot=64
__device__ unsigned g_wph[16 * 128],  g_wpl[16 * 128];   // proj:   Ktot=32
__device__ unsigned g_w1h[128 * 128], g_w1l[128 * 128];  // layer1: Ktot=256
__device__ unsigned g_w2h[128 * 128], g_w2l[128 * 128];  // layer2: Ktot=256

// ---------------- bf16 helpers ----------------
__device__ __forceinline__ unsigned packbf(float lo, float hi) {
    unsigned d;
    asm("cvt.rn.bf16x2.f32 %0, %1, %2;" : "=r"(d) : "f"(hi), "f"(lo));
    return d;
}
__device__ __forceinline__ float ubf_lo(unsigned p) { return __uint_as_float(p << 16); }
__device__ __forceinline__ float ubf_hi(unsigned p) { return __uint_as_float(p & 0xFFFF0000u); }

__device__ __forceinline__ void mma16(float* c,
    unsigned a0, unsigned a1, unsigned a2, unsigned a3,
    unsigned b0, unsigned b1)
{
    asm volatile(
        "mma.sync.aligned.m16n8k16.row.col.f32.bf16.bf16.f32 "
        "{%0,%1,%2,%3}, {%4,%5,%6,%7}, {%8,%9}, {%0,%1,%2,%3};"
        : "+f"(c[0]), "+f"(c[1]), "+f"(c[2]), "+f"(c[3])
        : "r"(a0), "r"(a1), "r"(a2), "r"(a3), "r"(b0), "r"(b1));
}

// ---------------- init: zero degrees + detect edge dtype ----------------
__global__ void k_init(const void* ei) {
    int i = blockIdx.x * blockDim.x + threadIdx.x;
    if (i < NN) g_deg[i] = 0;
    if (blockIdx.x == 0) {
        __shared__ int s_nz;
        if (threadIdx.x == 0) s_nz = 0;
        __syncthreads();
        const int* p = (const int*)ei;
        for (int j = threadIdx.x; j < 8192; j += blockDim.x)
            if (p[2 * j + 1] != 0) s_nz = 1;
        __syncthreads();
        if (threadIdx.x == 0) g_is64 = (s_nz == 0) ? 1 : 0;
    }
}

__device__ __forceinline__ int edge_at(const void* ei, long long idx) {
    if (g_is64) return (int)((const long long*)ei)[idx];
    return ((const int*)ei)[idx];
}

// ---------------- weight prep: fp32 -> packed bf16x2 hi/lo, all 4 at once -----
__global__ void k_wprep_all(
    const float* Wl0, const float* Wr0, const float* Wproj,
    const float* Wl1, const float* Wr1, const float* Wl2, const float* Wr2,
    unsigned* w0h, unsigned* w0l, unsigned* wph, unsigned* wpl,
    unsigned* w1h, unsigned* w1l, unsigned* w2h, unsigned* w2l)
{
    int which = blockIdx.y;
    const float *W1, *W2; int kin, Ktot; unsigned *oh, *ol;
    if (which == 0)      { W1 = Wl0;   W2 = Wr0;   kin = FIN; Ktot = 2 * FIN; oh = w0h; ol = w0l; }
    else if (which == 1) { W1 = Wproj; W2 = Wproj; kin = FIN; Ktot = FIN;     oh = wph; ol = wpl; }
    else if (which == 2) { W1 = Wl1;   W2 = Wr1;   kin = HD;  Ktot = 2 * HD;  oh = w1h; ol = w1l; }
    else                 { W1 = Wl2;   W2 = Wr2;   kin = HD;  Ktot = 2 * HD;  oh = w2h; ol = w2l; }
    int idx = blockIdx.x * blockDim.x + threadIdx.x;
    int total = (Ktot / 2) * 128;
    if (idx >= total) return;
    int kp = idx >> 7, col = idx & 127;
    int k = 2 * kp;
    const float* W = (k < kin) ? W1 : W2;
    int kk = (k < kin) ? k : (k - kin);
    float v0 = W[(size_t)kk * HD + col];
    float v1 = W[(size_t)(kk + 1) * HD + col];
    unsigned hp = packbf(v0, v1);
    oh[idx] = hp;
    ol[idx] = packbf(v0 - ubf_lo(hp), v1 - ubf_hi(hp));
}

// ---------------- x -> fp16 mirror ----------------
__global__ void k_xconv(const float* __restrict__ x, unsigned* __restrict__ xh) {
    int i = blockIdx.x * blockDim.x + threadIdx.x;
    if (i >= NN * 16) return;
    float2 v = *(const float2*)(x + 2 * (size_t)i);
    __half2 h = __floats2half2_rn(v.x, v.y);
    xh[i] = *(unsigned*)&h;
}

// ---------------- CSR build ----------------
__global__ void k_count(const void* ei) {
    int e = blockIdx.x * blockDim.x + threadIdx.x;
    if (e >= EE) return;
    atomicAdd(&g_deg[edge_at(ei, (long long)EE + e)], 1);
}

__global__ void k_scan1() {
    __shared__ int wsum[32];
    int i = blockIdx.x * 1024 + threadIdx.x;
    int v = (i < NN) ? g_deg[i] : 0;
    int lane = threadIdx.x & 31, w = threadIdx.x >> 5;
#pragma unroll
    for (int o = 16; o; o >>= 1) v += __shfl_xor_sync(0xFFFFFFFFu, v, o);
    if (lane == 0) wsum[w] = v;
    __syncthreads();
    if (w == 0) {
        int s = wsum[lane];
#pragma unroll
        for (int o = 16; o; o >>= 1) s += __shfl_xor_sync(0xFFFFFFFFu, s, o);
        if (lane == 0) g_bsum[blockIdx.x] = s;
    }
}

__global__ void k_scan2() {
    if (threadIdx.x == 0) {
        int run = 0;
        for (int i = 0; i < SCAN_B; i++) { int t = g_bsum[i]; g_bsum[i] = run; run += t; }
        g_rowptr[NN] = run;
    }
}

__global__ void k_scan3() {
    __shared__ int wsum[32];
    int b = blockIdx.x, tid = threadIdx.x;
    int i = b * 1024 + tid;
    int v = (i < NN) ? g_deg[i] : 0;
    int lane = tid & 31, w = tid >> 5;
    int x = v;
#pragma unroll
    for (int o = 1; o < 32; o <<= 1) {
        int t = __shfl_up_sync(0xFFFFFFFFu, x, o);
        if (lane >= o) x += t;
    }
    if (lane == 31) wsum[w] = x;
    __syncthreads();
    if (w == 0) {
        int s = wsum[lane];
#pragma unroll
        for (int o = 1; o < 32; o <<= 1) {
            int t = __shfl_up_sync(0xFFFFFFFFu, s, o);
            if (lane >= o) s += t;
        }
        wsum[lane] = s;
    }
    __syncthreads();
    int off = (w > 0) ? wsum[w - 1] : 0;
    int excl = x + off + g_bsum[b] - v;
    if (i < NN) { g_rowptr[i] = excl; g_pos[i] = excl; }
}

__global__ void k_fill(const void* ei) {
    int e = blockIdx.x * blockDim.x + threadIdx.x;
    if (e >= EE) return;
    int s = edge_at(ei, e);
    int d = edge_at(ei, (long long)EE + e);
    int p = atomicAdd(&g_pos[d], 1);
    g_col[p] = s;
}

// ---------------- mean aggregation over fp16 mirrors ----------------
// DIM=32: 16 lanes per node, each lane owns one half2 (cols 2l, 2l+1)
__global__ void k_agg32h(const unsigned* __restrict__ xh, float* __restrict__ agg) {
    int t = blockIdx.x * blockDim.x + threadIdx.x;
    int node = t >> 4;
    int l = t & 15;
    if (node >= NN) return;
    int beg = g_rowptr[node], end = g_rowptr[node + 1];
    float inv = 1.f / fmaxf((float)(end - beg), 1.f);
    float ax = 0.f, ay = 0.f;
    int e = beg;
    for (; e + 4 <= end; e += 4) {
        int s0 = g_col[e], s1 = g_col[e + 1], s2 = g_col[e + 2], s3 = g_col[e + 3];
        unsigned u0 = xh[(size_t)s0 * 16 + l];
        unsigned u1 = xh[(size_t)s1 * 16 + l];
        unsigned u2 = xh[(size_t)s2 * 16 + l];
        unsigned u3 = xh[(size_t)s3 * 16 + l];
        float2 f0 = __half22float2(*(__half2*)&u0);
        float2 f1 = __half22float2(*(__half2*)&u1);
        float2 f2 = __half22float2(*(__half2*)&u2);
        float2 f3 = __half22float2(*(__half2*)&u3);
        ax += f0.x + f1.x + f2.x + f3.x;
        ay += f0.y + f1.y + f2.y + f3.y;
    }
    for (; e < end; e++) {
        unsigned u = xh[(size_t)g_col[e] * 16 + l];
        float2 f = __half22float2(*(__half2*)&u);
        ax += f.x; ay += f.y;
    }
    *(float2*)(agg + (size_t)node * 32 + 2 * l) = make_float2(ax * inv, ay * inv);
}

// DIM=128: warp per node, each lane owns uint2 = 4 halves (cols lane*4..lane*4+3)
__global__ void k_agg128h(const uint2* __restrict__ hh, float* __restrict__ agg) {
    int w = (blockIdx.x * blockDim.x + threadIdx.x) >> 5;
    int lane = threadIdx.x & 31;
    if (w >= NN) return;
    int beg = g_rowptr[w], end = g_rowptr[w + 1];
    float inv = 1.f / fmaxf((float)(end - beg), 1.f);
    float ax = 0.f, ay = 0.f, az = 0.f, aw = 0.f;
    int e = beg;
    for (; e + 4 <= end; e += 4) {
        int s0 = g_col[e], s1 = g_col[e + 1], s2 = g_col[e + 2], s3 = g_col[e + 3];
        uint2 u0 = hh[(size_t)s0 * 32 + lane];
        uint2 u1 = hh[(size_t)s1 * 32 + lane];
        uint2 u2 = hh[(size_t)s2 * 32 + lane];
        uint2 u3 = hh[(size_t)s3 * 32 + lane];
        float2 a0 = __half22float2(*(__half2*)&u0.x), b0 = __half22float2(*(__half2*)&u0.y);
        float2 a1 = __half22float2(*(__half2*)&u1.x), b1 = __half22float2(*(__half2*)&u1.y);
        float2 a2 = __half22float2(*(__half2*)&u2.x), b2 = __half22float2(*(__half2*)&u2.y);
        float2 a3 = __half22float2(*(__half2*)&u3.x), b3 = __half22float2(*(__half2*)&u3.y);
        ax += a0.x + a1.x + a2.x + a3.x;
        ay += a0.y + a1.y + a2.y + a3.y;
        az += b0.x + b1.x + b2.x + b3.x;
        aw += b0.y + b1.y + b2.y + b3.y;
    }
    for (; e < end; e++) {
        uint2 u = hh[(size_t)g_col[e] * 32 + lane];
        float2 a = __half22float2(*(__half2*)&u.x), b = __half22float2(*(__half2*)&u.y);
        ax += a.x; ay += a.y; az += b.x; aw += b.y;
    }
    *(float4*)(agg + (size_t)w * 128 + lane * 4) =
        make_float4(ax * inv, ay * inv, az * inv, aw * inv);
}

// ---------------- fused bf16x3 GEMM (+bias) [+ LN+ReLU+res [+ head]] ---------
// MODE 0: raw write. MODE 1: relu(LN(.))+res (+ fp16 mirror). MODE 2: MODE1-head.
template <int MODE>
__global__ __launch_bounds__(256, 2) void k_mma_gemm(
    const float* __restrict__ A1, const float* __restrict__ A2,
    int kin, int Ktot,
    const unsigned* __restrict__ Wph, const unsigned* __restrict__ Wpl,
    const float* __restrict__ bias,
    const float* __restrict__ gamma, const float* __restrict__ beta,
    const float* __restrict__ res,
    float* __restrict__ out,
    unsigned* __restrict__ hh,
    const float* __restrict__ Wh, const float* __restrict__ bh,
    float* __restrict__ y)
{
    __shared__ unsigned sAh[8][132], sAl[8][132];
    __shared__ unsigned sWh[8][132], sWl[8][132];
    __shared__ float s_sum[4][128], s_sq[4][128];
    __shared__ float s_mu[128], s_rstd[128], s_y[128];

    const int tid = threadIdx.x;
    const int lane = tid & 31, wid = tid >> 5;
    const int wm = wid >> 2, wn = wid & 3;
    const int g = lane >> 2, tig = lane & 3;
    const int node0 = blockIdx.x * 128;

    float acc[4][4][4];
#pragma unroll
    for (int mt = 0; mt < 4; mt++)
#pragma unroll
        for (int nt = 0; nt < 4; nt++)
#pragma unroll
            for (int i = 0; i < 4; i++) acc[mt][nt][i] = 0.f;

    const int arow = tid >> 2;
    const int aq   = tid & 3;
    const int wrow = tid >> 5;
    const int wcol = (tid & 31) * 4;

    for (int k0 = 0; k0 < Ktot; k0 += 16) {
        const float* Asrc; int koff;
        if (k0 < kin) { Asrc = A1; koff = k0; } else { Asrc = A2; koff = k0 - kin; }
        const int kp0 = k0 >> 1;

#pragma unroll
        for (int h = 0; h < 2; h++) {
            int row = arow + h * 64;
            int node = node0 + row;
            float4 v = make_float4(0.f, 0.f, 0.f, 0.f);
            if (node < NN) v = *(const float4*)(Asrc + (size_t)node * kin + koff + aq * 4);
            unsigned hp0 = packbf(v.x, v.y);
            unsigned hp1 = packbf(v.z, v.w);
            unsigned lp0 = packbf(v.x - ubf_lo(hp0), v.y - ubf_hi(hp0));
            unsigned lp1 = packbf(v.z - ubf_lo(hp1), v.w - ubf_hi(hp1));
            sAh[2 * aq][row] = hp0; sAh[2 * aq + 1][row] = hp1;
            sAl[2 * aq][row] = lp0; sAl[2 * aq + 1][row] = lp1;
        }
        {
            *(uint4*)&sWh[wrow][wcol] = *(const uint4*)(Wph + (size_t)(kp0 + wrow) * 128 + wcol);
            *(uint4*)&sWl[wrow][wcol] = *(const uint4*)(Wpl + (size_t)(kp0 + wrow) * 128 + wcol);
        }
        __syncthreads();

        unsigned bh0[4], bh1[4], bl0[4], bl1[4];
#pragma unroll
        for (int nt = 0; nt < 4; nt++) {
            int n = wn * 32 + nt * 8 + g;
            bh0[nt] = sWh[tig][n];     bh1[nt] = sWh[tig + 4][n];
            bl0[nt] = sWl[tig][n];     bl1[nt] = sWl[tig + 4][n];
        }
#pragma unroll
        for (int mt = 0; mt < 4; mt++) {
            int r = wm * 64 + mt * 16 + g;
            unsigned a0h = sAh[tig][r],     a1h = sAh[tig][r + 8];
            unsigned a2h = sAh[tig + 4][r], a3h = sAh[tig + 4][r + 8];
            unsigned a0l = sAl[tig][r],     a1l = sAl[tig][r + 8];
            unsigned a2l = sAl[tig + 4][r], a3l = sAl[tig + 4][r + 8];
#pragma unroll
            for (int nt = 0; nt < 4; nt++) {
                mma16(acc[mt][nt], a0h, a1h, a2h, a3h, bh0[nt], bh1[nt]);
                mma16(acc[mt][nt], a0h, a1h, a2h, a3h, bl0[nt], bl1[nt]);
                mma16(acc[mt][nt], a0l, a1l, a2l, a3l, bh0[nt], bh1[nt]);
            }
        }
        __syncthreads();
    }

    if (MODE == 0) {
#pragma unroll
        for (int mt = 0; mt < 4; mt++) {
            int r0 = wm * 64 + mt * 16 + g;
            int n0 = node0 + r0, n1 = n0 + 8;
#pragma unroll
            for (int nt = 0; nt < 4; nt++) {
                int c0 = wn * 32 + nt * 8 + tig * 2;
                float bx = 0.f, by = 0.f;
                if (bias) { float2 b2 = *(const float2*)(bias + c0); bx = b2.x; by = b2.y; }
                if (n0 < NN)
                    *(float2*)(out + (size_t)n0 * HD + c0) =
                        make_float2(acc[mt][nt][0] + bx, acc[mt][nt][1] + by);
                if (n1 < NN)
                    *(float2*)(out + (size_t)n1 * HD + c0) =
                        make_float2(acc[mt][nt][2] + bx, acc[mt][nt][3] + by);
            }
        }
        return;
    }

#pragma unroll
    for (int mt = 0; mt < 4; mt++)
#pragma unroll
        for (int nt = 0; nt < 4; nt++) {
            int c0 = wn * 32 + nt * 8 + tig * 2;
            float2 b2 = *(const float2*)(bias + c0);
            acc[mt][nt][0] += b2.x; acc[mt][nt][1] += b2.y;
            acc[mt][nt][2] += b2.x; acc[mt][nt][3] += b2.y;
        }

#pragma unroll
    for (int mt = 0; mt < 4; mt++) {
        float s0 = 0.f, q0 = 0.f, s1 = 0.f, q1 = 0.f;
#pragma unroll
        for (int nt = 0; nt < 4; nt++) {
            float a0 = acc[mt][nt][0], a1 = acc[mt][nt][1];
            float a2 = acc[mt][nt][2], a3 = acc[mt][nt][3];
            s0 += a0 + a1; q0 += a0 * a0 + a1 * a1;
            s1 += a2 + a3; q1 += a2 * a2 + a3 * a3;
        }
#pragma unroll
        for (int o = 1; o < 4; o <<= 1) {
            s0 += __shfl_xor_sync(0xFFFFFFFFu, s0, o);
            q0 += __shfl_xor_sync(0xFFFFFFFFu, q0, o);
            s1 += __shfl_xor_sync(0xFFFFFFFFu, s1, o);
            q1 += __shfl_xor_sync(0xFFFFFFFFu, q1, o);
        }
        if (tig == 0) {
            int r0 = wm * 64 + mt * 16 + g;
            s_sum[wn][r0] = s0;     s_sq[wn][r0] = q0;
            s_sum[wn][r0 + 8] = s1; s_sq[wn][r0 + 8] = q1;
        }
    }
    __syncthreads();
    if (tid < 128) {
        float s = s_sum[0][tid] + s_sum[1][tid] + s_sum[2][tid] + s_sum[3][tid];
        float q = s_sq[0][tid] + s_sq[1][tid] + s_sq[2][tid] + s_sq[3][tid];
        float mu = s * (1.f / 128.f);
        float var = q * (1.f / 128.f) - mu * mu;
        s_mu[tid] = mu;
        s_rstd[tid] = rsqrtf(var + 1e-5f);
        if (MODE == 2) s_y[tid] = 0.f;
    }
    __syncthreads();

#pragma unroll
    for (int mt = 0; mt < 4; mt++) {
        int r0 = wm * 64 + mt * 16 + g, r1 = r0 + 8;
        int n0 = node0 + r0, n1 = node0 + r1;
        float mu0 = s_mu[r0], rs0 = s_rstd[r0];
        float mu1 = s_mu[r1], rs1 = s_rstd[r1];
        float y0 = 0.f, y1 = 0.f;
#pragma unroll
        for (int nt = 0; nt < 4; nt++) {
            int c0 = wn * 32 + nt * 8 + tig * 2;
            float2 g2 = *(const float2*)(gamma + c0);
            float2 b2 = *(const float2*)(beta + c0);
            float v00 = fmaxf((acc[mt][nt][0] - mu0) * rs0 * g2.x + b2.x, 0.f);
            float v01 = fmaxf((acc[mt][nt][1] - mu0) * rs0 * g2.y + b2.y, 0.f);
            float v10 = fmaxf((acc[mt][nt][2] - mu1) * rs1 * g2.x + b2.x, 0.f);
            float v11 = fmaxf((acc[mt][nt][3] - mu1) * rs1 * g2.y + b2.y, 0.f);
            if (n0 < NN) {
                float2 r2 = *(const float2*)(res + (size_t)n0 * HD + c0);
                v00 += r2.x; v01 += r2.y;
                *(float2*)(out + (size_t)n0 * HD + c0) = make_float2(v00, v01);
                if (MODE == 1) {
                    __half2 hv = __floats2half2_rn(v00, v01);
                    hh[(size_t)n0 * 64 + (c0 >> 1)] = *(unsigned*)&hv;
                }
            }
            if (n1 < NN) {
                float2 r2 = *(const float2*)(res + (size_t)n1 * HD + c0);
                v10 += r2.x; v11 += r2.y;
                *(float2*)(out + (size_t)n1 * HD + c0) = make_float2(v10, v11);
                if (MODE == 1) {
                    __half2 hv = __floats2half2_rn(v10, v11);
                    hh[(size_t)n1 * 64 + (c0 >> 1)] = *(unsigned*)&hv;
                }
            }
            if (MODE == 2) {
                float2 w2 = *(const float2*)(Wh + c0);
                y0 += v00 * w2.x + v01 * w2.y;
                y1 += v10 * w2.x + v11 * w2.y;
            }
        }
        if (MODE == 2) {
#pragma unroll
            for (int o = 1; o < 4; o <<= 1) {
                y0 += __shfl_xor_sync(0xFFFFFFFFu, y0, o);
                y1 += __shfl_xor_sync(0xFFFFFFFFu, y1, o);
            }
            if (tig == 0) {
                atomicAdd(&s_y[r0], y0);
                atomicAdd(&s_y[r1], y1);
            }
        }
    }
    if (MODE == 2) {
        __syncthreads();
        if (tid < 128 && node0 + tid < NN)
            y[node0 + tid] = s_y[tid] + bh[0];
    }
}

// ---------------- launcher ----------------
extern "C" void kernel_launch(void* const* d_in, const int* in_sizes, int n_in,
                              void* d_out, int out_size)
{
    const float* x     = (const float*)d_in[0];
    const void*  ei    = d_in[1];
    const float* Wl0   = (const float*)d_in[2];
    const float* bl0   = (const float*)d_in[3];
    const float* Wr0   = (const float*)d_in[4];
    const float* g0    = (const float*)d_in[5];
    const float* be0   = (const float*)d_in[6];
    const float* Wl1   = (const float*)d_in[7];
    const float* bl1   = (const float*)d_in[8];
    const float* Wr1   = (const float*)d_in[9];
    const float* g1    = (const float*)d_in[10];
    const float* be1   = (const float*)d_in[11];
    const float* Wl2   = (const float*)d_in[12];
    const float* bl2   = (const float*)d_in[13];
    const float* Wr2   = (const float*)d_in[14];
    const float* g2    = (const float*)d_in[15];
    const float* be2   = (const float*)d_in[16];
    const float* Wproj = (const float*)d_in[17];
    const float* Wh    = (const float*)d_in[18];
    const float* bh    = (const float*)d_in[19];

    float* out = (float*)d_out;

    float *pA, *pB, *pAgg;
    cudaGetSymbolAddress((void**)&pA,   g_bufA);
    cudaGetSymbolAddress((void**)&pB,   g_bufB);
    cudaGetSymbolAddress((void**)&pAgg, g_agg);
    uint2* pHH;  unsigned* pXH;
    cudaGetSymbolAddress((void**)&pHH, g_hh);
    cudaGetSymbolAddress((void**)&pXH, g_xh);
    unsigned *w0h, *w0l, *wph, *wpl, *w1h, *w1l, *w2h, *w2l;
    cudaGetSymbolAddress((void**)&w0h, g_w0h); cudaGetSymbolAddress((void**)&w0l, g_w0l);
    cudaGetSymbolAddress((void**)&wph, g_wph); cudaGetSymbolAddress((void**)&wpl, g_wpl);
    cudaGetSymbolAddress((void**)&w1h, g_w1h); cudaGetSymbolAddress((void**)&w1l, g_w1l);
    cudaGetSymbolAddress((void**)&w2h, g_w2h); cudaGetSymbolAddress((void**)&w2l, g_w2l);

    float* hout = (out_size >= NN + NN * HD) ? (out + NN) : pA;

    const int TB = 256;
    dim3 gN((NN + TB - 1) / TB), gE((EE + TB - 1) / TB);
    dim3 gWarp((NN + 7) / 8);
    dim3 gGemm((NN + 127) / 128);
    dim3 gAgg32((NN * 16 + TB - 1) / TB);

    // CSR build + weight prep + x fp16 mirror
    k_init<<<gN, TB>>>(ei);
    k_wprep_all<<<dim3(64, 4), 256>>>(Wl0, Wr0, Wproj, Wl1, Wr1, Wl2, Wr2,
                                      w0h, w0l, wph, wpl, w1h, w1l, w2h, w2l);
    k_xconv<<<(NN * 16 + TB - 1) / TB, TB>>>(x, pXH);
    k_count<<<gE, TB>>>(ei);
    k_scan1<<<SCAN_B, 1024>>>();
    k_scan2<<<1, 32>>>();
    k_scan3<<<SCAN_B, 1024>>>();
    k_fill<<<gE, TB>>>(ei);

    // ---- layer 0 ----
    k_agg32h<<<gAgg32, TB>>>(pXH, pAgg);
    k_mma_gemm<0><<<gGemm, TB>>>(x, x, FIN, FIN, wph, wpl, nullptr,
                                 nullptr, nullptr, nullptr, pB, nullptr,
                                 nullptr, nullptr, nullptr);
    k_mma_gemm<1><<<gGemm, TB>>>(pAgg, x, FIN, 2 * FIN, w0h, w0l, bl0,
                                 g0, be0, pB, pA, (unsigned*)pHH,
                                 nullptr, nullptr, nullptr);

    // ---- layer 1 ----
    k_agg128h<<<gWarp, TB>>>(pHH, pAgg);
    k_mma_gemm<1><<<gGemm, TB>>>(pAgg, pA, HD, 2 * HD, w1h, w1l, bl1,
                                 g1, be1, pA, pB, (unsigned*)pHH,
                                 nullptr, nullptr, nullptr);

    // ---- layer 2 (+ fused head) ----
    k_agg128h<<<gWarp, TB>>>(pHH, pAgg);
    k_mma_gemm<2><<<gGemm, TB>>>(pAgg, pB, HD, 2 * HD, w2h, w2l, bl2,
                                 g2, be2, pB, hout, nullptr,
                                 Wh, bh, out);
}

// round 5
// speedup vs baseline: 2.4353x; 1.0383x over previous
#include <cuda_runtime.h>
#include <cuda_bf16.h>
#include <cuda_fp16.h>
#include <cstdint>

#define NN 100000
#define EE 1600000
#define FIN 32
#define HD 128
#define SCAN_B 98                    // ceil(NN/1024)
#define ZB ((NN + 255) / 256)        // 391 blocks for zero-deg
#define XB ((NN * 16 + 255) / 256)   // 6250 blocks for xconv

// ---------------- persistent device scratch (no allocs allowed) ----------------
__device__ float g_bufA[(size_t)NN * HD];
__device__ float g_bufB[(size_t)NN * HD];
__device__ float g_agg [(size_t)NN * HD];
__device__ uint4 g_hh  [(size_t)NN * 16];   // fp16 mirror of current h (128 halves/row)
__device__ unsigned g_xh[(size_t)NN * 16];  // fp16 mirror of x (32 halves/row)
__device__ int   g_deg[NN];
__device__ int   g_rowptr[NN + 1];
__device__ int   g_pos[NN];
__device__ int   g_col[EE];
__device__ int   g_bsum[SCAN_B];
__device__ int   g_is64;

// packed bf16x2 (hi,lo) weights, layout [kp][col] with kp = k/2, 128 cols
__device__ unsigned g_w0h[32 * 128],  g_w0l[32 * 128];   // layer0: Ktot=64
__device__ unsigned g_wph[16 * 128],  g_wpl[16 * 128];   // proj:   Ktot=32
__device__ unsigned g_w1h[128 * 128], g_w1l[128 * 128];  // layer1: Ktot=256
__device__ unsigned g_w2h[128 * 128], g_w2l[128 * 128];  // layer2: Ktot=256

// ---------------- bf16 helpers ----------------
__device__ __forceinline__ unsigned packbf(float lo, float hi) {
    unsigned d;
    asm("cvt.rn.bf16x2.f32 %0, %1, %2;" : "=r"(d) : "f"(hi), "f"(lo));
    return d;
}
__device__ __forceinline__ float ubf_lo(unsigned p) { return __uint_as_float(p << 16); }
__device__ __forceinline__ float ubf_hi(unsigned p) { return __uint_as_float(p & 0xFFFF0000u); }

__device__ __forceinline__ void mma16(float* c,
    unsigned a0, unsigned a1, unsigned a2, unsigned a3,
    unsigned b0, unsigned b1)
{
    asm volatile(
        "mma.sync.aligned.m16n8k16.row.col.f32.bf16.bf16.f32 "
        "{%0,%1,%2,%3}, {%4,%5,%6,%7}, {%8,%9}, {%0,%1,%2,%3};"
        : "+f"(c[0]), "+f"(c[1]), "+f"(c[2]), "+f"(c[3])
        : "r"(a0), "r"(a1), "r"(a2), "r"(a3), "r"(b0), "r"(b1));
}

__device__ __forceinline__ int edge_at(const void* ei, long long idx) {
    if (g_is64) return (int)((const long long*)ei)[idx];
    return ((const int*)ei)[idx];
}

// ---------------- merged prologue: zero deg + detect + wprep + xconv ----------
__global__ void k_prologue(const void* ei, const float* __restrict__ x,
    unsigned* __restrict__ xh,
    const float* Wl0, const float* Wr0, const float* Wproj,
    const float* Wl1, const float* Wr1, const float* Wl2, const float* Wr2,
    unsigned* w0h, unsigned* w0l, unsigned* wph, unsigned* wpl,
    unsigned* w1h, unsigned* w1l, unsigned* w2h, unsigned* w2l)
{
    int b = blockIdx.x;
    int tid = threadIdx.x;
    if (b < ZB) {
        int i = b * 256 + tid;
        if (i < NN) g_deg[i] = 0;
        if (b == 0) {
            __shared__ int s_nz;
            if (tid == 0) s_nz = 0;
            __syncthreads();
            const int* p = (const int*)ei;
            for (int j = tid; j < 8192; j += 256)
                if (p[2 * j + 1] != 0) s_nz = 1;
            __syncthreads();
            if (tid == 0) g_is64 = (s_nz == 0) ? 1 : 0;
        }
        return;
    }
    b -= ZB;
    if (b < 256) {
        int which = b >> 6;
        const float *W1, *W2; int kin, Ktot; unsigned *oh, *ol;
        if (which == 0)      { W1 = Wl0;   W2 = Wr0;   kin = FIN; Ktot = 2 * FIN; oh = w0h; ol = w0l; }
        else if (which == 1) { W1 = Wproj; W2 = Wproj; kin = FIN; Ktot = FIN;     oh = wph; ol = wpl; }
        else if (which == 2) { W1 = Wl1;   W2 = Wr1;   kin = HD;  Ktot = 2 * HD;  oh = w1h; ol = w1l; }
        else                 { W1 = Wl2;   W2 = Wr2;   kin = HD;  Ktot = 2 * HD;  oh = w2h; ol = w2l; }
        int idx = (b & 63) * 256 + tid;
        int total = (Ktot / 2) * 128;
        if (idx >= total) return;
        int kp = idx >> 7, col = idx & 127;
        int k = 2 * kp;
        const float* W = (k < kin) ? W1 : W2;
        int kk = (k < kin) ? k : (k - kin);
        float v0 = W[(size_t)kk * HD + col];
        float v1 = W[(size_t)(kk + 1) * HD + col];
        unsigned hp = packbf(v0, v1);
        oh[idx] = hp;
        ol[idx] = packbf(v0 - ubf_lo(hp), v1 - ubf_hi(hp));
        return;
    }
    b -= 256;
    {
        int i = b * 256 + tid;
        if (i >= NN * 16) return;
        float2 v = *(const float2*)(x + 2 * (size_t)i);
        __half2 h = __floats2half2_rn(v.x, v.y);
        xh[i] = *(unsigned*)&h;
    }
}

// ---------------- CSR build ----------------
__global__ void k_count(const void* ei) {
    int e = blockIdx.x * blockDim.x + threadIdx.x;
    if (e >= EE) return;
    atomicAdd(&g_deg[edge_at(ei, (long long)EE + e)], 1);
}

__global__ void k_scan1() {
    __shared__ int wsum[32];
    int i = blockIdx.x * 1024 + threadIdx.x;
    int v = (i < NN) ? g_deg[i] : 0;
    int lane = threadIdx.x & 31, w = threadIdx.x >> 5;
#pragma unroll
    for (int o = 16; o; o >>= 1) v += __shfl_xor_sync(0xFFFFFFFFu, v, o);
    if (lane == 0) wsum[w] = v;
    __syncthreads();
    if (w == 0) {
        int s = wsum[lane];
#pragma unroll
        for (int o = 16; o; o >>= 1) s += __shfl_xor_sync(0xFFFFFFFFu, s, o);
        if (lane == 0) g_bsum[blockIdx.x] = s;
    }
}

// per-block exclusive scan; block offset computed inline from g_bsum
__global__ void k_scan3() {
    __shared__ int wsum[32];
    __shared__ int s_off;
    int b = blockIdx.x, tid = threadIdx.x;
    int lane = tid & 31, w = tid >> 5;
    if (w == 0) {
        int s = 0;
        for (int i = lane; i < SCAN_B; i += 32)
            if (i < b) s += g_bsum[i];
#pragma unroll
        for (int o = 16; o; o >>= 1) s += __shfl_xor_sync(0xFFFFFFFFu, s, o);
        if (lane == 0) s_off = s;
    }
    int i = b * 1024 + tid;
    int v = (i < NN) ? g_deg[i] : 0;
    int x = v;
#pragma unroll
    for (int o = 1; o < 32; o <<= 1) {
        int t = __shfl_up_sync(0xFFFFFFFFu, x, o);
        if (lane >= o) x += t;
    }
    if (lane == 31) wsum[w] = x;
    __syncthreads();
    if (w == 0) {
        int s = wsum[lane];
#pragma unroll
        for (int o = 1; o < 32; o <<= 1) {
            int t = __shfl_up_sync(0xFFFFFFFFu, s, o);
            if (lane >= o) s += t;
        }
        wsum[lane] = s;
    }
    __syncthreads();
    int off = (w > 0) ? wsum[w - 1] : 0;
    int excl = x + off + s_off - v;
    if (i < NN) { g_rowptr[i] = excl; g_pos[i] = excl; }
    if (b == 0 && tid == 0) g_rowptr[NN] = EE;
}

__global__ void k_fill(const void* ei) {
    int e = blockIdx.x * blockDim.x + threadIdx.x;
    if (e >= EE) return;
    int s = edge_at(ei, e);
    int d = edge_at(ei, (long long)EE + e);
    int p = atomicAdd(&g_pos[d], 1);
    g_col[p] = s;
}

// ---------------- mean aggregation over fp16 mirrors ----------------
// DIM=32: 16 lanes per node, each lane owns one half2 (cols 2l, 2l+1)
__global__ void k_agg32h(const unsigned* __restrict__ xh, float* __restrict__ agg) {
    int t = blockIdx.x * blockDim.x + threadIdx.x;
    int node = t >> 4;
    int l = t & 15;
    if (node >= NN) return;
    int beg = g_rowptr[node], end = g_rowptr[node + 1];
    float inv = 1.f / fmaxf((float)(end - beg), 1.f);
    float ax = 0.f, ay = 0.f;
    int e = beg;
    for (; e + 4 <= end; e += 4) {
        int s0 = g_col[e], s1 = g_col[e + 1], s2 = g_col[e + 2], s3 = g_col[e + 3];
        unsigned u0 = xh[(size_t)s0 * 16 + l];
        unsigned u1 = xh[(size_t)s1 * 16 + l];
        unsigned u2 = xh[(size_t)s2 * 16 + l];
        unsigned u3 = xh[(size_t)s3 * 16 + l];
        float2 f0 = __half22float2(*(__half2*)&u0);
        float2 f1 = __half22float2(*(__half2*)&u1);
        float2 f2 = __half22float2(*(__half2*)&u2);
        float2 f3 = __half22float2(*(__half2*)&u3);
        ax += f0.x + f1.x + f2.x + f3.x;
        ay += f0.y + f1.y + f2.y + f3.y;
    }
    for (; e < end; e++) {
        unsigned u = xh[(size_t)g_col[e] * 16 + l];
        float2 f = __half22float2(*(__half2*)&u);
        ax += f.x; ay += f.y;
    }
    *(float2*)(agg + (size_t)node * 32 + 2 * l) = make_float2(ax * inv, ay * inv);
}

// DIM=128: HALF-warp per node. Each 16-lane group loads one full 256B row per
// edge with a single LDG.128/lane (uint4 = 8 halves, cols 8l..8l+7).
__global__ void k_agg128h(const uint4* __restrict__ hh, float* __restrict__ agg) {
    int w = (blockIdx.x * blockDim.x + threadIdx.x) >> 5;
    int lane = threadIdx.x & 31;
    int half = lane >> 4;
    int l = lane & 15;
    int node = w * 2 + half;
    if (node >= NN) return;
    int beg = g_rowptr[node], end = g_rowptr[node + 1];
    float inv = 1.f / fmaxf((float)(end - beg), 1.f);
    float a0 = 0.f, a1 = 0.f, a2 = 0.f, a3 = 0.f;
    float a4 = 0.f, a5 = 0.f, a6 = 0.f, a7 = 0.f;
    int e = beg;
    for (; e + 2 <= end; e += 2) {
        int s0 = g_col[e], s1 = g_col[e + 1];
        uint4 u0 = hh[(size_t)s0 * 16 + l];
        uint4 u1 = hh[(size_t)s1 * 16 + l];
        float2 p0 = __half22float2(*(__half2*)&u0.x), q0 = __half22float2(*(__half2*)&u1.x);
        float2 p1 = __half22float2(*(__half2*)&u0.y), q1 = __half22float2(*(__half2*)&u1.y);
        float2 p2 = __half22float2(*(__half2*)&u0.z), q2 = __half22float2(*(__half2*)&u1.z);
        float2 p3 = __half22float2(*(__half2*)&u0.w), q3 = __half22float2(*(__half2*)&u1.w);
        a0 += p0.x + q0.x; a1 += p0.y + q0.y;
        a2 += p1.x + q1.x; a3 += p1.y + q1.y;
        a4 += p2.x + q2.x; a5 += p2.y + q2.y;
        a6 += p3.x + q3.x; a7 += p3.y + q3.y;
    }
    if (e < end) {
        uint4 u = hh[(size_t)g_col[e] * 16 + l];
        float2 p0 = __half22float2(*(__half2*)&u.x);
        float2 p1 = __half22float2(*(__half2*)&u.y);
        float2 p2 = __half22float2(*(__half2*)&u.z);
        float2 p3 = __half22float2(*(__half2*)&u.w);
        a0 += p0.x; a1 += p0.y; a2 += p1.x; a3 += p1.y;
        a4 += p2.x; a5 += p2.y; a6 += p3.x; a7 += p3.y;
    }
    float* dst = agg + (size_t)node * 128 + l * 8;
    *(float4*)dst       = make_float4(a0 * inv, a1 * inv, a2 * inv, a3 * inv);
    *(float4*)(dst + 4) = make_float4(a4 * inv, a5 * inv, a6 * inv, a7 * inv);
}

// ---------------- fused bf16x3 GEMM (+bias) [+ LN+ReLU+res [+ head]] ---------
// MODE 0: raw write. MODE 1: relu(LN(.))+res (+ fp16 mirror). MODE 2: MODE1-head.
template <int MODE>
__global__ __launch_bounds__(256, 2) void k_mma_gemm(
    const float* __restrict__ A1, const float* __restrict__ A2,
    int kin, int Ktot,
    const unsigned* __restrict__ Wph, const unsigned* __restrict__ Wpl,
    const float* __restrict__ bias,
    const float* __restrict__ gamma, const float* __restrict__ beta,
    const float* __restrict__ res,
    float* __restrict__ out,
    unsigned* __restrict__ hh,
    const float* __restrict__ Wh, const float* __restrict__ bh,
    float* __restrict__ y)
{
    __shared__ unsigned sAh[8][132], sAl[8][132];
    __shared__ unsigned sWh[8][132], sWl[8][132];
    __shared__ float s_sum[4][128], s_sq[4][128];
    __shared__ float s_mu[128], s_rstd[128], s_y[128];

    const int tid = threadIdx.x;
    const int lane = tid & 31, wid = tid >> 5;
    const int wm = wid >> 2, wn = wid & 3;
    const int g = lane >> 2, tig = lane & 3;
    const int node0 = blockIdx.x * 128;

    float acc[4][4][4];
#pragma unroll
    for (int mt = 0; mt < 4; mt++)
#pragma unroll
        for (int nt = 0; nt < 4; nt++)
#pragma unroll
            for (int i = 0; i < 4; i++) acc[mt][nt][i] = 0.f;

    const int arow = tid >> 2;
    const int aq   = tid & 3;
    const int wrow = tid >> 5;
    const int wcol = (tid & 31) * 4;

    for (int k0 = 0; k0 < Ktot; k0 += 16) {
        const float* Asrc; int koff;
        if (k0 < kin) { Asrc = A1; koff = k0; } else { Asrc = A2; koff = k0 - kin; }
        const int kp0 = k0 >> 1;

#pragma unroll
        for (int h = 0; h < 2; h++) {
            int row = arow + h * 64;
            int node = node0 + row;
            float4 v = make_float4(0.f, 0.f, 0.f, 0.f);
            if (node < NN) v = *(const float4*)(Asrc + (size_t)node * kin + koff + aq * 4);
            unsigned hp0 = packbf(v.x, v.y);
            unsigned hp1 = packbf(v.z, v.w);
            unsigned lp0 = packbf(v.x - ubf_lo(hp0), v.y - ubf_hi(hp0));
            unsigned lp1 = packbf(v.z - ubf_lo(hp1), v.w - ubf_hi(hp1));
            sAh[2 * aq][row] = hp0; sAh[2 * aq + 1][row] = hp1;
            sAl[2 * aq][row] = lp0; sAl[2 * aq + 1][row] = lp1;
        }
        {
            *(uint4*)&sWh[wrow][wcol] = *(const uint4*)(Wph + (size_t)(kp0 + wrow) * 128 + wcol);
            *(uint4*)&sWl[wrow][wcol] = *(const uint4*)(Wpl + (size_t)(kp0 + wrow) * 128 + wcol);
        }
        __syncthreads();

        unsigned bh0[4], bh1[4], bl0[4], bl1[4];
#pragma unroll
        for (int nt = 0; nt < 4; nt++) {
            int n = wn * 32 + nt * 8 + g;
            bh0[nt] = sWh[tig][n];     bh1[nt] = sWh[tig + 4][n];
            bl0[nt] = sWl[tig][n];     bl1[nt] = sWl[tig + 4][n];
        }
#pragma unroll
        for (int mt = 0; mt < 4; mt++) {
            int r = wm * 64 + mt * 16 + g;
            unsigned a0h = sAh[tig][r],     a1h = sAh[tig][r + 8];
            unsigned a2h = sAh[tig + 4][r], a3h = sAh[tig + 4][r + 8];
            unsigned a0l = sAl[tig][r],     a1l = sAl[tig][r + 8];
            unsigned a2l = sAl[tig + 4][r], a3l = sAl[tig + 4][r + 8];
#pragma unroll
            for (int nt = 0; nt < 4; nt++) {
                mma16(acc[mt][nt], a0h, a1h, a2h, a3h, bh0[nt], bh1[nt]);
                mma16(acc[mt][nt], a0h, a1h, a2h, a3h, bl0[nt], bl1[nt]);
                mma16(acc[mt][nt], a0l, a1l, a2l, a3l, bh0[nt], bh1[nt]);
            }
        }
        __syncthreads();
    }

    if (MODE == 0) {
#pragma unroll
        for (int mt = 0; mt < 4; mt++) {
            int r0 = wm * 64 + mt * 16 + g;
            int n0 = node0 + r0, n1 = n0 + 8;
#pragma unroll
            for (int nt = 0; nt < 4; nt++) {
                int c0 = wn * 32 + nt * 8 + tig * 2;
                float bx = 0.f, by = 0.f;
                if (bias) { float2 b2 = *(const float2*)(bias + c0); bx = b2.x; by = b2.y; }
                if (n0 < NN)
                    *(float2*)(out + (size_t)n0 * HD + c0) =
                        make_float2(acc[mt][nt][0] + bx, acc[mt][nt][1] + by);
                if (n1 < NN)
                    *(float2*)(out + (size_t)n1 * HD + c0) =
                        make_float2(acc[mt][nt][2] + bx, acc[mt][nt][3] + by);
            }
        }
        return;
    }

#pragma unroll
    for (int mt = 0; mt < 4; mt++)
#pragma unroll
        for (int nt = 0; nt < 4; nt++) {
            int c0 = wn * 32 + nt * 8 + tig * 2;
            float2 b2 = *(const float2*)(bias + c0);
            acc[mt][nt][0] += b2.x; acc[mt][nt][1] += b2.y;
            acc[mt][nt][2] += b2.x; acc[mt][nt][3] += b2.y;
        }

#pragma unroll
    for (int mt = 0; mt < 4; mt++) {
        float s0 = 0.f, q0 = 0.f, s1 = 0.f, q1 = 0.f;
#pragma unroll
        for (int nt = 0; nt < 4; nt++) {
            float a0 = acc[mt][nt][0], a1 = acc[mt][nt][1];
            float a2 = acc[mt][nt][2], a3 = acc[mt][nt][3];
            s0 += a0 + a1; q0 += a0 * a0 + a1 * a1;
            s1 += a2 + a3; q1 += a2 * a2 + a3 * a3;
        }
#pragma unroll
        for (int o = 1; o < 4; o <<= 1) {
            s0 += __shfl_xor_sync(0xFFFFFFFFu, s0, o);
            q0 += __shfl_xor_sync(0xFFFFFFFFu, q0, o);
            s1 += __shfl_xor_sync(0xFFFFFFFFu, s1, o);
            q1 += __shfl_xor_sync(0xFFFFFFFFu, q1, o);
        }
        if (tig == 0) {
            int r0 = wm * 64 + mt * 16 + g;
            s_sum[wn][r0] = s0;     s_sq[wn][r0] = q0;
            s_sum[wn][r0 + 8] = s1; s_sq[wn][r0 + 8] = q1;
        }
    }
    __syncthreads();
    if (tid < 128) {
        float s = s_sum[0][tid] + s_sum[1][tid] + s_sum[2][tid] + s_sum[3][tid];
        float q = s_sq[0][tid] + s_sq[1][tid] + s_sq[2][tid] + s_sq[3][tid];
        float mu = s * (1.f / 128.f);
        float var = q * (1.f / 128.f) - mu * mu;
        s_mu[tid] = mu;
        s_rstd[tid] = rsqrtf(var + 1e-5f);
        if (MODE == 2) s_y[tid] = 0.f;
    }
    __syncthreads();

#pragma unroll
    for (int mt = 0; mt < 4; mt++) {
        int r0 = wm * 64 + mt * 16 + g, r1 = r0 + 8;
        int n0 = node0 + r0, n1 = node0 + r1;
        float mu0 = s_mu[r0], rs0 = s_rstd[r0];
        float mu1 = s_mu[r1], rs1 = s_rstd[r1];
        float y0 = 0.f, y1 = 0.f;
#pragma unroll
        for (int nt = 0; nt < 4; nt++) {
            int c0 = wn * 32 + nt * 8 + tig * 2;
            float2 g2 = *(const float2*)(gamma + c0);
            float2 b2 = *(const float2*)(beta + c0);
            float v00 = fmaxf((acc[mt][nt][0] - mu0) * rs0 * g2.x + b2.x, 0.f);
            float v01 = fmaxf((acc[mt][nt][1] - mu0) * rs0 * g2.y + b2.y, 0.f);
            float v10 = fmaxf((acc[mt][nt][2] - mu1) * rs1 * g2.x + b2.x, 0.f);
            float v11 = fmaxf((acc[mt][nt][3] - mu1) * rs1 * g2.y + b2.y, 0.f);
            if (n0 < NN) {
                float2 r2 = *(const float2*)(res + (size_t)n0 * HD + c0);
                v00 += r2.x; v01 += r2.y;
                *(float2*)(out + (size_t)n0 * HD + c0) = make_float2(v00, v01);
                if (MODE == 1) {
                    __half2 hv = __floats2half2_rn(v00, v01);
                    hh[(size_t)n0 * 64 + (c0 >> 1)] = *(unsigned*)&hv;
                }
            }
            if (n1 < NN) {
                float2 r2 = *(const float2*)(res + (size_t)n1 * HD + c0);
                v10 += r2.x; v11 += r2.y;
                *(float2*)(out + (size_t)n1 * HD + c0) = make_float2(v10, v11);
                if (MODE == 1) {
                    __half2 hv = __floats2half2_rn(v10, v11);
                    hh[(size_t)n1 * 64 + (c0 >> 1)] = *(unsigned*)&hv;
                }
            }
            if (MODE == 2) {
                float2 w2 = *(const float2*)(Wh + c0);
                y0 += v00 * w2.x + v01 * w2.y;
                y1 += v10 * w2.x + v11 * w2.y;
            }
        }
        if (MODE == 2) {
#pragma unroll
            for (int o = 1; o < 4; o <<= 1) {
                y0 += __shfl_xor_sync(0xFFFFFFFFu, y0, o);
                y1 += __shfl_xor_sync(0xFFFFFFFFu, y1, o);
            }
            if (tig == 0) {
                atomicAdd(&s_y[r0], y0);
                atomicAdd(&s_y[r1], y1);
            }
        }
    }
    if (MODE == 2) {
        __syncthreads();
        if (tid < 128 && node0 + tid < NN)
            y[node0 + tid] = s_y[tid] + bh[0];
    }
}

// ---------------- launcher ----------------
extern "C" void kernel_launch(void* const* d_in, const int* in_sizes, int n_in,
                              void* d_out, int out_size)
{
    const float* x     = (const float*)d_in[0];
    const void*  ei    = d_in[1];
    const float* Wl0   = (const float*)d_in[2];
    const float* bl0   = (const float*)d_in[3];
    const float* Wr0   = (const float*)d_in[4];
    const float* g0    = (const float*)d_in[5];
    const float* be0   = (const float*)d_in[6];
    const float* Wl1   = (const float*)d_in[7];
    const float* bl1   = (const float*)d_in[8];
    const float* Wr1   = (const float*)d_in[9];
    const float* g1    = (const float*)d_in[10];
    const float* be1   = (const float*)d_in[11];
    const float* Wl2   = (const float*)d_in[12];
    const float* bl2   = (const float*)d_in[13];
    const float* Wr2   = (const float*)d_in[14];
    const float* g2    = (const float*)d_in[15];
    const float* be2   = (const float*)d_in[16];
    const float* Wproj = (const float*)d_in[17];
    const float* Wh    = (const float*)d_in[18];
    const float* bh    = (const float*)d_in[19];

    float* out = (float*)d_out;

    float *pA, *pB, *pAgg;
    cudaGetSymbolAddress((void**)&pA,   g_bufA);
    cudaGetSymbolAddress((void**)&pB,   g_bufB);
    cudaGetSymbolAddress((void**)&pAgg, g_agg);
    uint4* pHH;  unsigned* pXH;
    cudaGetSymbolAddress((void**)&pHH, g_hh);
    cudaGetSymbolAddress((void**)&pXH, g_xh);
    unsigned *w0h, *w0l, *wph, *wpl, *w1h, *w1l, *w2h, *w2l;
    cudaGetSymbolAddress((void**)&w0h, g_w0h); cudaGetSymbolAddress((void**)&w0l, g_w0l);
    cudaGetSymbolAddress((void**)&wph, g_wph); cudaGetSymbolAddress((void**)&wpl, g_wpl);
    cudaGetSymbolAddress((void**)&w1h, g_w1h); cudaGetSymbolAddress((void**)&w1l, g_w1l);
    cudaGetSymbolAddress((void**)&w2h, g_w2h); cudaGetSymbolAddress((void**)&w2l, g_w2l);

    float* hout = (out_size >= NN + NN * HD) ? (out + NN) : pA;

    const int TB = 256;
    dim3 gE((EE + TB - 1) / TB);
    dim3 gGemm((NN + 127) / 128);
    dim3 gAgg32((NN * 16 + TB - 1) / TB);
    dim3 gAgg128((NN / 2 + 7) / 8);          // half-warp per node, 8 warps/block
    dim3 gPro(ZB + 256 + XB);

    // prologue (zero deg + detect + wprep + xconv) then CSR build
    k_prologue<<<gPro, TB>>>(ei, x, pXH, Wl0, Wr0, Wproj, Wl1, Wr1, Wl2, Wr2,
                             w0h, w0l, wph, wpl, w1h, w1l, w2h, w2l);
    k_count<<<gE, TB>>>(ei);
    k_scan1<<<SCAN_B, 1024>>>();
    k_scan3<<<SCAN_B, 1024>>>();
    k_fill<<<gE, TB>>>(ei);

    // ---- layer 0 ----
    k_agg32h<<<gAgg32, TB>>>(pXH, pAgg);
    k_mma_gemm<0><<<gGemm, TB>>>(x, x, FIN, FIN, wph, wpl, nullptr,
                                 nullptr, nullptr, nullptr, pB, nullptr,
                                 nullptr, nullptr, nullptr);
    k_mma_gemm<1><<<gGemm, TB>>>(pAgg, x, FIN, 2 * FIN, w0h, w0l, bl0,
                                 g0, be0, pB, pA, (unsigned*)pHH,
                                 nullptr, nullptr, nullptr);

    // ---- layer 1 ----
    k_agg128h<<<gAgg128, TB>>>(pHH, pAgg);
    k_mma_gemm<1><<<gGemm, TB>>>(pAgg, pA, HD, 2 * HD, w1h, w1l, bl1,
                                 g1, be1, pA, pB, (unsigned*)pHH,
                                 nullptr, nullptr, nullptr);

    // ---- layer 2 (+ fused head) ----
    k_agg128h<<<gAgg128, TB>>>(pHH, pAgg);
    k_mma_gemm<2><<<gGemm, TB>>>(pAgg, pB, HD, 2 * HD, w2h, w2l, bl2,
                                 g2, be2, pB, hout, nullptr,
                                 Wh, bh, out);
}